// round 1
// baseline (speedup 1.0000x reference)
#include <cuda_runtime.h>
#include <math.h>

#define BN_EPS 1e-5f
#define SLOPE  0.1f

// Problem dims
#define BSZ    32
#define HO     19            // output spatial
#define NPOS   (BSZ*HO*HO)   // 11552
#define C_CAT  1280
#define C_PRE  1024
#define K2     (C_CAT*9)     // 11520
#define M_HEAD 600

// Padded concat buffer: [B][1280][21][21], zero halo of 1 on each side.
__device__ float g_concat[BSZ * C_CAT * 21 * 21];   // 72.25 MB
__device__ float g_pre[BSZ * C_PRE * HO * HO];      // 47.3 MB

// ---------------------------------------------------------------------------
// Kernel 1: conv1x1 (512->64) + BN + leaky + reorg(2), writes channels 0..255
// of g_concat interior. One block per (b, y) row of the 38x38 conv output.
// 128 threads: 16 c-groups (4 ch each) x 8 x-groups (5 x each).
// ---------------------------------------------------------------------------
__global__ void conv1_reorg_kernel(const float* __restrict__ stage5,
                                   const float* __restrict__ w1,
                                   const float* __restrict__ g1,
                                   const float* __restrict__ b1,
                                   const float* __restrict__ m1,
                                   const float* __restrict__ v1) {
    __shared__ float s5s[64 * 38 + 16];   // +pad: tolerates x<40 junk reads
    __shared__ float ws[64 * 68];         // [cc][c], stride 68 (bank-friendly, 16B aligned)

    const int y   = blockIdx.x;   // 0..37
    const int b   = blockIdx.y;   // 0..31
    const int tid = threadIdx.x;  // 0..127
    const int cg  = tid & 15;
    const int xg  = tid >> 4;
    const int cbase = cg * 4;

    float acc[4][5];
#pragma unroll
    for (int j = 0; j < 4; j++)
#pragma unroll
        for (int i = 0; i < 5; i++) acc[j][i] = 0.f;

    for (int ci0 = 0; ci0 < 512; ci0 += 64) {
        __syncthreads();
        for (int idx = tid; idx < 64 * 38; idx += 128) {
            int cc = idx / 38, xx = idx - cc * 38;
            s5s[idx] = stage5[((b * 512 + ci0 + cc) * 38 + y) * 38 + xx];
        }
        for (int idx = tid; idx < 64 * 64; idx += 128) {
            int c = idx >> 6, cc = idx & 63;               // coalesced over cc
            ws[cc * 68 + c] = w1[c * 512 + ci0 + cc];
        }
        __syncthreads();
#pragma unroll 4
        for (int cc = 0; cc < 64; cc++) {
            float4 wv = *(const float4*)&ws[cc * 68 + cbase];
#pragma unroll
            for (int i = 0; i < 5; i++) {
                int x = xg + 8 * i;                        // may reach 39: padded smem
                float sv = s5s[cc * 38 + x];
                acc[0][i] += wv.x * sv;
                acc[1][i] += wv.y * sv;
                acc[2][i] += wv.z * sv;
                acc[3][i] += wv.w * sv;
            }
        }
    }

    const int sh = y & 1, ho = y >> 1;
#pragma unroll
    for (int j = 0; j < 4; j++) {
        int c = cbase + j;
        float sc = g1[c] * rsqrtf(v1[c] + BN_EPS);
        float sf = b1[c] - m1[c] * sc;
#pragma unroll
        for (int i = 0; i < 5; i++) {
            int x = xg + 8 * i;
            if (x < 38) {
                float v = acc[j][i] * sc + sf;
                v = v > 0.f ? v : SLOPE * v;
                int ch = sh * 128 + (x & 1) * 64 + c;      // reorg channel
                int wo = x >> 1;
                g_concat[((b * 1280 + ch) * 21 + 1 + ho) * 21 + 1 + wo] = v;
            }
        }
    }
}

// ---------------------------------------------------------------------------
// Kernel 2: copy stage6 [32,1024,19,19] into g_concat channels 256..1279.
// ---------------------------------------------------------------------------
__global__ void copy_stage6_kernel(const float* __restrict__ stage6) {
    const int total = BSZ * 1024 * 361;
    for (int idx = blockIdx.x * blockDim.x + threadIdx.x; idx < total;
         idx += gridDim.x * blockDim.x) {
        int b   = idx / (1024 * 361);
        int rem = idx - b * (1024 * 361);
        int c   = rem / 361;
        int yx  = rem - c * 361;
        int yy  = yx / 19, xx = yx - yy * 19;
        g_concat[((b * 1280 + 256 + c) * 21 + 1 + yy) * 21 + 1 + xx] = stage6[idx];
    }
}

// ---------------------------------------------------------------------------
// Kernel 3: conv3x3 as implicit GEMM. M=1024, N=11552, K=11520.
// A = w2 viewed [1024][11520] row-major (k=(ci,r,s), s fastest == memory order).
// B = gather from padded g_concat: addr = boff(p) + ci*441 + r*21 + s.
// CTA 128x128x8, 256 threads, 8x8 micro-tile, single-sync double buffering.
// Epilogue: BN + leaky -> g_pre[b][co][yx].
// ---------------------------------------------------------------------------
__global__ __launch_bounds__(256, 2)
void conv2_kernel(const float* __restrict__ w2,
                  const float* __restrict__ g2, const float* __restrict__ b2,
                  const float* __restrict__ m2, const float* __restrict__ v2) {
    __shared__ float As[2][8][128];
    __shared__ float Bs[2][8][128];
    const float* __restrict__ cin = g_concat;

    const int tid = threadIdx.x;
    const int m0  = blockIdx.y * 128;
    const int p0  = blockIdx.x * 128;
    const int ty  = tid >> 4, tx = tid & 15;

    // B-gather setup: this thread loads (k0 + b_k, p0 + b_c + 32*i)
    const int b_k = tid >> 5;
    const int b_c = tid & 31;
    int  boff[4];
    bool bval[4];
#pragma unroll
    for (int i = 0; i < 4; i++) {
        int p = p0 + b_c + 32 * i;
        bval[i] = p < NPOS;
        int pp = bval[i] ? p : 0;
        int bb = pp / 361;
        int yx = pp - bb * 361;
        int yy = yx / 19, xx = yx - yy * 19;
        boff[i] = bb * (1280 * 441) + yy * 21 + xx;
    }
    const int a_row = tid >> 1;
    const int a_k   = (tid & 1) * 4;

    float acc[8][8];
#pragma unroll
    for (int r = 0; r < 8; r++)
#pragma unroll
        for (int c = 0; c < 8; c++) acc[r][c] = 0.f;

    float4 a_pref;
    float  b_pref[4];
    // preload kt = 0
    {
        a_pref = *(const float4*)&w2[(m0 + a_row) * K2 + a_k];
        int k  = b_k;
        int ci = k / 9; int rs = k - ci * 9;
        int rr = rs / 3; int ss = rs - rr * 3;
        int koff = ci * 441 + rr * 21 + ss;
#pragma unroll
        for (int i = 0; i < 4; i++)
            b_pref[i] = bval[i] ? cin[boff[i] + koff] : 0.f;
    }
    As[0][a_k + 0][a_row] = a_pref.x;
    As[0][a_k + 1][a_row] = a_pref.y;
    As[0][a_k + 2][a_row] = a_pref.z;
    As[0][a_k + 3][a_row] = a_pref.w;
#pragma unroll
    for (int i = 0; i < 4; i++) Bs[0][b_k][b_c + 32 * i] = b_pref[i];
    __syncthreads();

    int buf = 0;
    for (int kt = 0; kt < K2 / 8; ++kt) {
        const bool more = (kt + 1) < (K2 / 8);
        if (more) {
            int k0n = (kt + 1) * 8;
            a_pref = *(const float4*)&w2[(m0 + a_row) * K2 + k0n + a_k];
            int k  = k0n + b_k;
            int ci = k / 9; int rs = k - ci * 9;
            int rr = rs / 3; int ss = rs - rr * 3;
            int koff = ci * 441 + rr * 21 + ss;
#pragma unroll
            for (int i = 0; i < 4; i++)
                b_pref[i] = bval[i] ? cin[boff[i] + koff] : 0.f;
        }
#pragma unroll
        for (int kk = 0; kk < 8; kk++) {
            float4 a0 = *(const float4*)&As[buf][kk][ty * 8];
            float4 a1 = *(const float4*)&As[buf][kk][ty * 8 + 4];
            float4 c0 = *(const float4*)&Bs[buf][kk][tx * 8];
            float4 c1 = *(const float4*)&Bs[buf][kk][tx * 8 + 4];
            float av[8] = {a0.x, a0.y, a0.z, a0.w, a1.x, a1.y, a1.z, a1.w};
            float bv[8] = {c0.x, c0.y, c0.z, c0.w, c1.x, c1.y, c1.z, c1.w};
#pragma unroll
            for (int r = 0; r < 8; r++)
#pragma unroll
                for (int c = 0; c < 8; c++) acc[r][c] += av[r] * bv[c];
        }
        if (more) {
            int nb = buf ^ 1;
            As[nb][a_k + 0][a_row] = a_pref.x;
            As[nb][a_k + 1][a_row] = a_pref.y;
            As[nb][a_k + 2][a_row] = a_pref.z;
            As[nb][a_k + 3][a_row] = a_pref.w;
#pragma unroll
            for (int i = 0; i < 4; i++) Bs[nb][b_k][b_c + 32 * i] = b_pref[i];
            __syncthreads();
            buf = nb;
        }
    }

    // Epilogue: BN + leaky -> g_pre
#pragma unroll
    for (int r = 0; r < 8; r++) {
        int co = m0 + ty * 8 + r;
        float sc = g2[co] * rsqrtf(v2[co] + BN_EPS);
        float sf = b2[co] - m2[co] * sc;
#pragma unroll
        for (int c = 0; c < 8; c++) {
            int p = p0 + tx * 8 + c;
            if (p < NPOS) {
                float v = acc[r][c] * sc + sf;
                v = v > 0.f ? v : SLOPE * v;
                int bb = p / 361;
                int yx = p - bb * 361;
                g_pre[(bb * 1024 + co) * 361 + yx] = v;
            }
        }
    }
}

// ---------------------------------------------------------------------------
// Kernel 4: head einsum. out[(b*600+m)*361+yx] = sum_k pre[b][k][yx]*W[m][k] + bias[m]
// A = meta rows (stride 1025, last elem is bias). M=600, N=11552, K=1024.
// ---------------------------------------------------------------------------
__global__ __launch_bounds__(256, 2)
void head_kernel(const float* __restrict__ meta, float* __restrict__ out) {
    __shared__ float As[2][8][128];
    __shared__ float Bs[2][8][128];
    const float* __restrict__ pre = g_pre;

    const int tid = threadIdx.x;
    const int m0  = blockIdx.y * 128;
    const int p0  = blockIdx.x * 128;
    const int ty  = tid >> 4, tx = tid & 15;

    const int b_k = tid >> 5;
    const int b_c = tid & 31;
    int  boff[4];
    bool bval[4];
#pragma unroll
    for (int i = 0; i < 4; i++) {
        int p = p0 + b_c + 32 * i;
        bval[i] = p < NPOS;
        int pp = bval[i] ? p : 0;
        int bb = pp / 361;
        int yx = pp - bb * 361;
        boff[i] = bb * (1024 * 361) + yx;
    }
    const int a_row = tid >> 1;
    const int a_k   = (tid & 1) * 4;
    const int rowg  = m0 + a_row;
    const int rowc  = rowg < M_HEAD ? rowg : (M_HEAD - 1);
    const float az  = rowg < M_HEAD ? 1.f : 0.f;

    float acc[8][8];
#pragma unroll
    for (int r = 0; r < 8; r++)
#pragma unroll
        for (int c = 0; c < 8; c++) acc[r][c] = 0.f;

    float a_pref[4];
    float b_pref[4];
    {
#pragma unroll
        for (int j = 0; j < 4; j++)
            a_pref[j] = meta[rowc * 1025 + a_k + j] * az;
        int k = b_k;
#pragma unroll
        for (int i = 0; i < 4; i++)
            b_pref[i] = bval[i] ? pre[boff[i] + k * 361] : 0.f;
    }
#pragma unroll
    for (int j = 0; j < 4; j++) As[0][a_k + j][a_row] = a_pref[j];
#pragma unroll
    for (int i = 0; i < 4; i++) Bs[0][b_k][b_c + 32 * i] = b_pref[i];
    __syncthreads();

    int buf = 0;
    for (int kt = 0; kt < 1024 / 8; ++kt) {
        const bool more = (kt + 1) < (1024 / 8);
        if (more) {
            int k0n = (kt + 1) * 8;
#pragma unroll
            for (int j = 0; j < 4; j++)
                a_pref[j] = meta[rowc * 1025 + k0n + a_k + j] * az;
            int k = k0n + b_k;
#pragma unroll
            for (int i = 0; i < 4; i++)
                b_pref[i] = bval[i] ? pre[boff[i] + k * 361] : 0.f;
        }
#pragma unroll
        for (int kk = 0; kk < 8; kk++) {
            float4 a0 = *(const float4*)&As[buf][kk][ty * 8];
            float4 a1 = *(const float4*)&As[buf][kk][ty * 8 + 4];
            float4 c0 = *(const float4*)&Bs[buf][kk][tx * 8];
            float4 c1 = *(const float4*)&Bs[buf][kk][tx * 8 + 4];
            float av[8] = {a0.x, a0.y, a0.z, a0.w, a1.x, a1.y, a1.z, a1.w};
            float bv[8] = {c0.x, c0.y, c0.z, c0.w, c1.x, c1.y, c1.z, c1.w};
#pragma unroll
            for (int r = 0; r < 8; r++)
#pragma unroll
                for (int c = 0; c < 8; c++) acc[r][c] += av[r] * bv[c];
        }
        if (more) {
            int nb = buf ^ 1;
#pragma unroll
            for (int j = 0; j < 4; j++) As[nb][a_k + j][a_row] = a_pref[j];
#pragma unroll
            for (int i = 0; i < 4; i++) Bs[nb][b_k][b_c + 32 * i] = b_pref[i];
            __syncthreads();
            buf = nb;
        }
    }

#pragma unroll
    for (int r = 0; r < 8; r++) {
        int m = m0 + ty * 8 + r;
        if (m < M_HEAD) {
            float bias = meta[m * 1025 + 1024];
#pragma unroll
            for (int c = 0; c < 8; c++) {
                int p = p0 + tx * 8 + c;
                if (p < NPOS) {
                    int bb = p / 361;
                    int yx = p - bb * 361;
                    out[(bb * 600 + m) * 361 + yx] = acc[r][c] + bias;
                }
            }
        }
    }
}

// ---------------------------------------------------------------------------
extern "C" void kernel_launch(void* const* d_in, const int* in_sizes, int n_in,
                              void* d_out, int out_size) {
    const float* stage6 = (const float*)d_in[0];
    const float* stage5 = (const float*)d_in[1];
    const float* w1     = (const float*)d_in[2];
    const float* g1     = (const float*)d_in[3];
    const float* b1     = (const float*)d_in[4];
    const float* m1     = (const float*)d_in[5];
    const float* v1     = (const float*)d_in[6];
    const float* w2     = (const float*)d_in[7];
    const float* g2     = (const float*)d_in[8];
    const float* b2     = (const float*)d_in[9];
    const float* m2     = (const float*)d_in[10];
    const float* v2     = (const float*)d_in[11];
    const float* meta   = (const float*)d_in[12];
    float* out = (float*)d_out;

    // Zero the padded concat buffer (halo must be 0 every call).
    void* pconcat = nullptr;
    cudaGetSymbolAddress(&pconcat, g_concat);
    cudaMemsetAsync(pconcat, 0, sizeof(float) * BSZ * C_CAT * 21 * 21, 0);

    conv1_reorg_kernel<<<dim3(38, 32), 128>>>(stage5, w1, g1, b1, m1, v1);
    copy_stage6_kernel<<<1024, 256>>>(stage6);
    conv2_kernel<<<dim3(91, 8), 256>>>(w2, g2, b2, m2, v2);
    head_kernel<<<dim3(91, 5), 256>>>(meta, out);
}

// round 7
// speedup vs baseline: 2.4580x; 2.4580x over previous
#include <cuda_runtime.h>
#include <cuda_bf16.h>
#include <stdint.h>
#include <math.h>

#define BN_EPS 1e-5f
#define SLOPE  0.1f
#define BSZ    32
#define HO     19
#define NPOS   (BSZ*HO*HO)    // 11552
#define K2     11520
#define KT2    (K2/32)        // 360
#define MHEAD  600
#define MHEAD_P 640
#define KH     1024
#define KTH    (KH/32)        // 32

typedef __nv_bfloat16 bf16;
typedef unsigned int u32;

// ---------------- device scratch (no allocs allowed) ----------------
__device__ bf16 g_cath[BSZ*21*21*1280];   // NHWC padded concat, hi
__device__ bf16 g_catl[BSZ*21*21*1280];   // lo
__device__ bf16 g_w2h[1024*K2];           // w2 repacked [co][(r*3+s)*1280+ci], hi
__device__ bf16 g_w2l[1024*K2];
__device__ bf16 g_clsh[MHEAD_P*KH];       // cls weights padded to 640 rows
__device__ bf16 g_clsl[MHEAD_P*KH];
__device__ bf16 g_preh[NPOS*KH];          // conv2 output [pos][co], hi
__device__ bf16 g_prel[NPOS*KH];

// ---------------- small PTX helpers ----------------
__device__ __forceinline__ void ldm_x4(u32 addr, u32 &q0, u32 &q1, u32 &q2, u32 &q3) {
    asm volatile("ldmatrix.sync.aligned.m8n8.x4.shared.b16 {%0,%1,%2,%3}, [%4];"
                 : "=r"(q0), "=r"(q1), "=r"(q2), "=r"(q3) : "r"(addr));
}
__device__ __forceinline__ void mma_bf16(float* c, const u32* a, const u32* b) {
    asm volatile("mma.sync.aligned.m16n8k16.row.col.f32.bf16.bf16.f32 "
                 "{%0,%1,%2,%3}, {%4,%5,%6,%7}, {%8,%9}, {%0,%1,%2,%3};"
                 : "+f"(c[0]), "+f"(c[1]), "+f"(c[2]), "+f"(c[3])
                 : "r"(a[0]), "r"(a[1]), "r"(a[2]), "r"(a[3]), "r"(b[0]), "r"(b[1]));
}
__device__ __forceinline__ void cp16(void* dst, const void* src) {
    u32 d = (u32)__cvta_generic_to_shared(dst);
    asm volatile("cp.async.cg.shared.global [%0], [%1], 16;" :: "r"(d), "l"(src));
}
#define CPCOMMIT() asm volatile("cp.async.commit_group;")
#define CPWAIT1()  asm volatile("cp.async.wait_group 1;" ::: "memory")

__device__ __forceinline__ void split_bf16(float v, bf16& h, bf16& l) {
    h = __float2bfloat16(v);
    l = __float2bfloat16(v - __bfloat162float(h));
}

// ---------------------------------------------------------------------------
// Shared MMA stage compute. SMEM stage layout (byte offsets from sb):
//   Ah @ 0, Al @ 10240, Bh @ 20480, Bl @ 30720. Row stride 80 bytes (32 bf16 + pad).
// Warp tile: 64(m) x 32(n). 8 warps as 2(m) x 4(n). Split-bf16: HH + HL + LH.
// ---------------------------------------------------------------------------
__device__ __forceinline__ void compute_stage(u32 sb, int lane, int wm, int wn,
                                              float (&acc)[4][4][4]) {
#pragma unroll
    for (int h = 0; h < 2; ++h) {
        u32 aH[4][4], aL[4][4], bH[4][2], bL[4][2];
#pragma unroll
        for (int mf = 0; mf < 4; ++mf) {
            int row = wm * 64 + mf * 16 + (lane & 15);
            u32 off = sb + row * 80 + h * 32 + (lane >> 4) * 16;
            ldm_x4(off,         aH[mf][0], aH[mf][1], aH[mf][2], aH[mf][3]);
            ldm_x4(off + 10240, aL[mf][0], aL[mf][1], aL[mf][2], aL[mf][3]);
        }
#pragma unroll
        for (int nf2 = 0; nf2 < 2; ++nf2) {
            int row = wn * 32 + nf2 * 16 + (lane & 15);
            u32 off = sb + 20480 + row * 80 + h * 32 + (lane >> 4) * 16;
            u32 q0, q1, q2, q3;
            ldm_x4(off, q0, q1, q2, q3);
            bH[nf2 * 2][0] = q0; bH[nf2 * 2 + 1][0] = q1;
            bH[nf2 * 2][1] = q2; bH[nf2 * 2 + 1][1] = q3;
            u32 s0, s1, s2, s3;
            ldm_x4(off + 10240, s0, s1, s2, s3);
            bL[nf2 * 2][0] = s0; bL[nf2 * 2 + 1][0] = s1;
            bL[nf2 * 2][1] = s2; bL[nf2 * 2 + 1][1] = s3;
        }
#pragma unroll
        for (int mf = 0; mf < 4; ++mf)
#pragma unroll
            for (int nf = 0; nf < 4; ++nf) {
                mma_bf16(acc[mf][nf], aH[mf], bH[nf]);
                mma_bf16(acc[mf][nf], aH[mf], bL[nf]);
                mma_bf16(acc[mf][nf], aL[mf], bH[nf]);
            }
    }
}

// ---------------------------------------------------------------------------
// conv1x1(512->64)+BN+leaky+reorg(2) -> NHWC bf16 hi/lo, channels 0..255
// ---------------------------------------------------------------------------
__global__ void conv1_reorg_kernel(const float* __restrict__ stage5,
                                   const float* __restrict__ w1,
                                   const float* __restrict__ g1,
                                   const float* __restrict__ b1,
                                   const float* __restrict__ m1,
                                   const float* __restrict__ v1) {
    __shared__ float s5s[64 * 38 + 16];
    __shared__ float ws[64 * 68];

    const int y = blockIdx.x, b = blockIdx.y, tid = threadIdx.x;
    const int cg = tid & 15, xg = tid >> 4, cbase = cg * 4;

    float acc[4][5];
#pragma unroll
    for (int j = 0; j < 4; j++)
#pragma unroll
        for (int i = 0; i < 5; i++) acc[j][i] = 0.f;

    for (int ci0 = 0; ci0 < 512; ci0 += 64) {
        __syncthreads();
        for (int idx = tid; idx < 64 * 38; idx += 128) {
            int cc = idx / 38, xx = idx - cc * 38;
            s5s[idx] = stage5[((b * 512 + ci0 + cc) * 38 + y) * 38 + xx];
        }
        for (int idx = tid; idx < 64 * 64; idx += 128) {
            int c = idx >> 6, cc = idx & 63;
            ws[cc * 68 + c] = w1[c * 512 + ci0 + cc];
        }
        __syncthreads();
#pragma unroll 4
        for (int cc = 0; cc < 64; cc++) {
            float4 wv = *(const float4*)&ws[cc * 68 + cbase];
#pragma unroll
            for (int i = 0; i < 5; i++) {
                float sv = s5s[cc * 38 + xg + 8 * i];
                acc[0][i] += wv.x * sv;
                acc[1][i] += wv.y * sv;
                acc[2][i] += wv.z * sv;
                acc[3][i] += wv.w * sv;
            }
        }
    }

    const int sh = y & 1, ho = y >> 1;
#pragma unroll
    for (int j = 0; j < 4; j++) {
        int c = cbase + j;
        float sc = g1[c] * rsqrtf(v1[c] + BN_EPS);
        float sf = b1[c] - m1[c] * sc;
#pragma unroll
        for (int i = 0; i < 5; i++) {
            int x = xg + 8 * i;
            if (x < 38) {
                float v = acc[j][i] * sc + sf;
                v = v > 0.f ? v : SLOPE * v;
                int ch = sh * 128 + (x & 1) * 64 + c;
                int wo = x >> 1;
                int addr = ((b * 21 + 1 + ho) * 21 + 1 + wo) * 1280 + ch;
                bf16 hv, lv; split_bf16(v, hv, lv);
                g_cath[addr] = hv; g_catl[addr] = lv;
            }
        }
    }
}

// ---------------------------------------------------------------------------
// stage6 [32,1024,19,19] fp32 -> NHWC bf16 hi/lo at channels 256..1279
// ---------------------------------------------------------------------------
__global__ void stage6_to_cat(const float* __restrict__ s6) {
    __shared__ float t[32][33];
    const int b = blockIdx.z, c0 = blockIdx.y * 32, yx0 = blockIdx.x * 32;
    const int tx = threadIdx.x, ty0 = threadIdx.y;
#pragma unroll
    for (int i = 0; i < 4; i++) {
        int ty = ty0 + i * 8;
        int yx = yx0 + tx;
        t[ty][tx] = (yx < 361) ? s6[(b * 1024 + c0 + ty) * 361 + yx] : 0.f;
    }
    __syncthreads();
#pragma unroll
    for (int i = 0; i < 4; i++) {
        int ty = ty0 + i * 8;
        int yx = yx0 + ty;
        if (yx >= 361) continue;
        int y = yx / 19, x = yx - y * 19;
        float v = t[tx][ty];
        int addr = ((b * 21 + 1 + y) * 21 + 1 + x) * 1280 + 256 + c0 + tx;
        bf16 hv, lv; split_bf16(v, hv, lv);
        g_cath[addr] = hv; g_catl[addr] = lv;
    }
}

// ---------------------------------------------------------------------------
// Weight repacks
// ---------------------------------------------------------------------------
__global__ void repack_w2(const float* __restrict__ w2) {
    int idx = blockIdx.x * 256 + threadIdx.x;
    if (idx >= 1024 * K2) return;
    int co = idx / K2, kk = idx - co * K2;
    int rs = kk / 1280, ci = kk - rs * 1280;
    float v = w2[(co * 1280 + ci) * 9 + rs];
    bf16 hv, lv; split_bf16(v, hv, lv);
    g_w2h[idx] = hv; g_w2l[idx] = lv;
}

__global__ void repack_cls(const float* __restrict__ meta) {
    int idx = blockIdx.x * 256 + threadIdx.x;
    if (idx >= MHEAD_P * KH) return;
    int m = idx >> 10, k = idx & 1023;
    float v = (m < MHEAD) ? meta[m * 1025 + k] : 0.f;
    bf16 hv, lv; split_bf16(v, hv, lv);
    g_clsh[idx] = hv; g_clsl[idx] = lv;
}

// ---------------------------------------------------------------------------
// conv3x3 implicit GEMM on tensor cores. M=1024, N=11552, K=11520.
// CTA 128x128, 8 warps (2m x 4n), warp 64x32, K-step 32, 3-stage cp.async.
// ---------------------------------------------------------------------------
#define SSTAGE 20480   // bf16 elements per stage (40960 bytes)

__global__ __launch_bounds__(256)
void conv2_mma(const float* __restrict__ g2, const float* __restrict__ b2,
               const float* __restrict__ m2, const float* __restrict__ v2) {
    extern __shared__ bf16 dyn[];
    const int tid = threadIdx.x, lane = tid & 31, warp = tid >> 5;
    const int wm = warp >> 2, wn = warp & 3;
    const int gq = lane >> 2, tig = lane & 3;
    const int m0 = blockIdx.x * 128, p0 = blockIdx.y * 128;
    const int arow = tid >> 2, ach = tid & 3;

    int rbase[2];
#pragma unroll
    for (int it = 0; it < 2; ++it) {
        int p = p0 + arow + it * 64;
        if (p >= NPOS) p = NPOS - 1;
        int b = p / 361, yx = p - b * 361, y = yx / 19, x = yx - y * 19;
        rbase[it] = ((b * 21 + y) * 21 + x) * 1280;
    }

    float acc[4][4][4];
#pragma unroll
    for (int mf = 0; mf < 4; mf++)
#pragma unroll
        for (int nf = 0; nf < 4; nf++)
#pragma unroll
            for (int e = 0; e < 4; e++) acc[mf][nf][e] = 0.f;

#define CONV2_LOAD(KT)                                                         \
    do {                                                                       \
        int kt_ = (KT);                                                        \
        bf16* base_ = dyn + (kt_ % 3) * SSTAGE;                                \
        int k0_ = kt_ * 32;                                                    \
        _Pragma("unroll")                                                      \
        for (int it = 0; it < 2; ++it) {                                       \
            int r_ = arow + it * 64;                                           \
            cp16(base_ + r_ * 40 + ach * 8,        g_w2h + (m0 + r_) * K2 + k0_ + ach * 8); \
            cp16(base_ + 5120 + r_ * 40 + ach * 8, g_w2l + (m0 + r_) * K2 + k0_ + ach * 8); \
        }                                                                      \
        int rs_ = kt_ / 40, ci0_ = (kt_ - rs_ * 40) * 32;                      \
        int rr_ = rs_ / 3, ss_ = rs_ - rr_ * 3;                                \
        int koff_ = (rr_ * 21 + ss_) * 1280 + ci0_;                            \
        _Pragma("unroll")                                                      \
        for (int it = 0; it < 2; ++it) {                                       \
            int r_ = arow + it * 64;                                           \
            cp16(base_ + 10240 + r_ * 40 + ach * 8, g_cath + rbase[it] + koff_ + ach * 8); \
            cp16(base_ + 15360 + r_ * 40 + ach * 8, g_catl + rbase[it] + koff_ + ach * 8); \
        }                                                                      \
    } while (0)

    CONV2_LOAD(0); CPCOMMIT();
    CONV2_LOAD(1); CPCOMMIT();
    for (int kt = 0; kt < KT2; ++kt) {
        CPWAIT1();
        __syncthreads();
        if (kt + 2 < KT2) CONV2_LOAD(kt + 2);
        CPCOMMIT();
        u32 sb = (u32)__cvta_generic_to_shared(dyn + (kt % 3) * SSTAGE);
        compute_stage(sb, lane, wm, wn, acc);
    }
#undef CONV2_LOAD

    // Epilogue: BN + leaky, transpose to [pos][co], split to bf16 hi/lo.
    __syncthreads();
    float* smf = (float*)dyn;            // [128 n][132 m] + sc[128] + sf[128]
#pragma unroll
    for (int mf = 0; mf < 4; ++mf)
#pragma unroll
        for (int nf = 0; nf < 4; ++nf)
#pragma unroll
            for (int e = 0; e < 4; ++e) {
                int m = wm * 64 + mf * 16 + gq + (e >> 1) * 8;
                int n = wn * 32 + nf * 8 + tig * 2 + (e & 1);
                smf[n * 132 + m] = acc[mf][nf][e];
            }
    if (tid < 128) {
        int co = m0 + tid;
        float sc = g2[co] * rsqrtf(v2[co] + BN_EPS);
        smf[128 * 132 + tid] = sc;
        smf[128 * 132 + 128 + tid] = b2[co] - m2[co] * sc;
    }
    __syncthreads();
    for (int idx = tid; idx < 128 * 128; idx += 256) {
        int n = idx >> 7, m = idx & 127;
        int p = p0 + n;
        if (p < NPOS) {
            float v = smf[n * 132 + m] * smf[128 * 132 + m] + smf[128 * 132 + 128 + m];
            v = v > 0.f ? v : SLOPE * v;
            bf16 hv, lv; split_bf16(v, hv, lv);
            int a = p * 1024 + m0 + m;
            g_preh[a] = hv; g_prel[a] = lv;
        }
    }
}

// ---------------------------------------------------------------------------
// Head GEMM: M=640(600), N=11552, K=1024. Same stage layout + compute.
// ---------------------------------------------------------------------------
__global__ __launch_bounds__(256)
void head_mma(const float* __restrict__ meta, float* __restrict__ out) {
    extern __shared__ bf16 dyn[];
    const int tid = threadIdx.x, lane = tid & 31, warp = tid >> 5;
    const int wm = warp >> 2, wn = warp & 3;
    const int gq = lane >> 2, tig = lane & 3;
    const int m0 = blockIdx.x * 128, p0 = blockIdx.y * 128;
    const int arow = tid >> 2, ach = tid & 3;

    int rbase[2];
#pragma unroll
    for (int it = 0; it < 2; ++it) {
        int p = p0 + arow + it * 64;
        if (p >= NPOS) p = NPOS - 1;
        rbase[it] = p * KH;
    }

    float acc[4][4][4];
#pragma unroll
    for (int mf = 0; mf < 4; mf++)
#pragma unroll
        for (int nf = 0; nf < 4; nf++)
#pragma unroll
            for (int e = 0; e < 4; e++) acc[mf][nf][e] = 0.f;

#define HEAD_LOAD(KT)                                                          \
    do {                                                                       \
        int kt_ = (KT);                                                        \
        bf16* base_ = dyn + (kt_ % 3) * SSTAGE;                                \
        int k0_ = kt_ * 32;                                                    \
        _Pragma("unroll")                                                      \
        for (int it = 0; it < 2; ++it) {                                       \
            int r_ = arow + it * 64;                                           \
            cp16(base_ + r_ * 40 + ach * 8,         g_clsh + (m0 + r_) * KH + k0_ + ach * 8); \
            cp16(base_ + 5120 + r_ * 40 + ach * 8,  g_clsl + (m0 + r_) * KH + k0_ + ach * 8); \
            cp16(base_ + 10240 + r_ * 40 + ach * 8, g_preh + rbase[it] + k0_ + ach * 8); \
            cp16(base_ + 15360 + r_ * 40 + ach * 8, g_prel + rbase[it] + k0_ + ach * 8); \
        }                                                                      \
    } while (0)

    HEAD_LOAD(0); CPCOMMIT();
    HEAD_LOAD(1); CPCOMMIT();
    for (int kt = 0; kt < KTH; ++kt) {
        CPWAIT1();
        __syncthreads();
        if (kt + 2 < KTH) HEAD_LOAD(kt + 2);
        CPCOMMIT();
        u32 sb = (u32)__cvta_generic_to_shared(dyn + (kt % 3) * SSTAGE);
        compute_stage(sb, lane, wm, wn, acc);
    }
#undef HEAD_LOAD

    // Epilogue: + bias, scatter to out[(b*600+m)*361+yx]
#pragma unroll
    for (int mf = 0; mf < 4; ++mf) {
        int mb = m0 + wm * 64 + mf * 16 + gq;
#pragma unroll
        for (int e2 = 0; e2 < 2; ++e2) {
            int m = mb + e2 * 8;
            if (m < MHEAD) {
                float bias = meta[m * 1025 + 1024];
#pragma unroll
                for (int nf = 0; nf < 4; ++nf)
#pragma unroll
                    for (int e1 = 0; e1 < 2; ++e1) {
                        int n = p0 + wn * 32 + nf * 8 + tig * 2 + e1;
                        if (n < NPOS) {
                            int b = n / 361, yx = n - b * 361;
                            out[(b * 600 + m) * 361 + yx] = acc[mf][nf][e2 * 2 + e1] + bias;
                        }
                    }
            }
        }
    }
}

// ---------------------------------------------------------------------------
extern "C" void kernel_launch(void* const* d_in, const int* in_sizes, int n_in,
                              void* d_out, int out_size) {
    const float* stage6 = (const float*)d_in[0];
    const float* stage5 = (const float*)d_in[1];
    const float* w1     = (const float*)d_in[2];
    const float* g1     = (const float*)d_in[3];
    const float* b1     = (const float*)d_in[4];
    const float* m1     = (const float*)d_in[5];
    const float* v1     = (const float*)d_in[6];
    const float* w2     = (const float*)d_in[7];
    const float* g2     = (const float*)d_in[8];
    const float* b2     = (const float*)d_in[9];
    const float* m2     = (const float*)d_in[10];
    const float* v2     = (const float*)d_in[11];
    const float* meta   = (const float*)d_in[12];
    float* out = (float*)d_out;

    void* p;
    cudaGetSymbolAddress(&p, g_cath);
    cudaMemsetAsync(p, 0, sizeof(bf16) * BSZ * 441 * 1280, 0);
    cudaGetSymbolAddress(&p, g_catl);
    cudaMemsetAsync(p, 0, sizeof(bf16) * BSZ * 441 * 1280, 0);

    cudaFuncSetAttribute(conv2_mma, cudaFuncAttributeMaxDynamicSharedMemorySize, 3 * SSTAGE * 2);
    cudaFuncSetAttribute(head_mma,  cudaFuncAttributeMaxDynamicSharedMemorySize, 3 * SSTAGE * 2);

    conv1_reorg_kernel<<<dim3(38, 32), 128>>>(stage5, w1, g1, b1, m1, v1);
    stage6_to_cat<<<dim3(12, 32, 32), dim3(32, 8)>>>(stage6);
    repack_w2<<<(1024 * K2 + 255) / 256, 256>>>(w2);
    repack_cls<<<(MHEAD_P * KH + 255) / 256, 256>>>(meta);

    conv2_mma<<<dim3(8, 91), 256, 3 * SSTAGE * 2>>>(g2, b2, m2, v2);
    head_mma<<<dim3(5, 91), 256, 3 * SSTAGE * 2>>>(meta, out);
}

// round 9
// speedup vs baseline: 2.7463x; 1.1173x over previous
#include <cuda_runtime.h>
#include <cuda_bf16.h>
#include <stdint.h>
#include <math.h>

#define BN_EPS 1e-5f
#define SLOPE  0.1f
#define BSZ    32
#define HO     19
#define NPOS   (BSZ*HO*HO)    // 11552
#define K2     11520
#define KT2    (K2/32)        // 360
#define MHEAD  600
#define MHEAD_P 640
#define KH     1024
#define KTH    (KH/32)        // 32

typedef __nv_bfloat16 bf16;
typedef unsigned int u32;

// ---------------- device scratch (no allocs allowed) ----------------
__device__ bf16 g_cath[BSZ*21*21*1280];   // NHWC padded concat, hi
__device__ bf16 g_catl[BSZ*21*21*1280];   // lo
__device__ bf16 g_w2h[1024*K2];           // w2 repacked [co][(r*3+s)*1280+ci], hi
__device__ bf16 g_w2l[1024*K2];
__device__ bf16 g_clsh[MHEAD_P*KH];       // cls weights padded to 640 rows
__device__ bf16 g_clsl[MHEAD_P*KH];
__device__ bf16 g_preh[NPOS*KH];          // conv2 output [pos][co], hi
__device__ bf16 g_prel[NPOS*KH];

// ---------------- small PTX helpers ----------------
__device__ __forceinline__ void ldm_x4(u32 addr, u32 &q0, u32 &q1, u32 &q2, u32 &q3) {
    asm volatile("ldmatrix.sync.aligned.m8n8.x4.shared.b16 {%0,%1,%2,%3}, [%4];"
                 : "=r"(q0), "=r"(q1), "=r"(q2), "=r"(q3) : "r"(addr));
}
__device__ __forceinline__ void mma_bf16(float* c, const u32* a, const u32* b) {
    asm volatile("mma.sync.aligned.m16n8k16.row.col.f32.bf16.bf16.f32 "
                 "{%0,%1,%2,%3}, {%4,%5,%6,%7}, {%8,%9}, {%0,%1,%2,%3};"
                 : "+f"(c[0]), "+f"(c[1]), "+f"(c[2]), "+f"(c[3])
                 : "r"(a[0]), "r"(a[1]), "r"(a[2]), "r"(a[3]), "r"(b[0]), "r"(b[1]));
}
__device__ __forceinline__ void cp16(void* dst, const void* src) {
    u32 d = (u32)__cvta_generic_to_shared(dst);
    asm volatile("cp.async.cg.shared.global [%0], [%1], 16;" :: "r"(d), "l"(src));
}
#define CPCOMMIT() asm volatile("cp.async.commit_group;")
#define CPWAIT1()  asm volatile("cp.async.wait_group 1;" ::: "memory")
#define CPWAIT0()  asm volatile("cp.async.wait_group 0;" ::: "memory")

__device__ __forceinline__ void split_bf16(float v, bf16& h, bf16& l) {
    h = __float2bfloat16(v);
    l = __float2bfloat16(v - __bfloat162float(h));
}

// ---------------------------------------------------------------------------
// Shared MMA stage compute. SMEM stage layout (byte offsets from sb):
//   Ah @ 0, Al @ 10240, Bh @ 20480, Bl @ 30720. Row stride 80 bytes (32 bf16 + pad).
// Warp tile: 64(m) x 32(n). 8 warps as 2(m) x 4(n). Split-bf16: HH + HL + LH.
// ---------------------------------------------------------------------------
__device__ __forceinline__ void compute_stage(u32 sb, int lane, int wm, int wn,
                                              float (&acc)[4][4][4]) {
#pragma unroll
    for (int h = 0; h < 2; ++h) {
        u32 aH[4][4], aL[4][4], bH[4][2], bL[4][2];
#pragma unroll
        for (int mf = 0; mf < 4; ++mf) {
            int row = wm * 64 + mf * 16 + (lane & 15);
            u32 off = sb + row * 80 + h * 32 + (lane >> 4) * 16;
            ldm_x4(off,         aH[mf][0], aH[mf][1], aH[mf][2], aH[mf][3]);
            ldm_x4(off + 10240, aL[mf][0], aL[mf][1], aL[mf][2], aL[mf][3]);
        }
#pragma unroll
        for (int nf2 = 0; nf2 < 2; ++nf2) {
            int row = wn * 32 + nf2 * 16 + (lane & 15);
            u32 off = sb + 20480 + row * 80 + h * 32 + (lane >> 4) * 16;
            u32 q0, q1, q2, q3;
            ldm_x4(off, q0, q1, q2, q3);
            bH[nf2 * 2][0] = q0; bH[nf2 * 2 + 1][0] = q1;
            bH[nf2 * 2][1] = q2; bH[nf2 * 2 + 1][1] = q3;
            u32 s0, s1, s2, s3;
            ldm_x4(off + 10240, s0, s1, s2, s3);
            bL[nf2 * 2][0] = s0; bL[nf2 * 2 + 1][0] = s1;
            bL[nf2 * 2][1] = s2; bL[nf2 * 2 + 1][1] = s3;
        }
#pragma unroll
        for (int mf = 0; mf < 4; ++mf)
#pragma unroll
            for (int nf = 0; nf < 4; ++nf) {
                mma_bf16(acc[mf][nf], aH[mf], bH[nf]);
                mma_bf16(acc[mf][nf], aH[mf], bL[nf]);
                mma_bf16(acc[mf][nf], aL[mf], bH[nf]);
            }
    }
}

// ---------------------------------------------------------------------------
// conv1x1(512->64)+BN+leaky+reorg(2) -> NHWC bf16 hi/lo, channels 0..255
// ---------------------------------------------------------------------------
__global__ void conv1_reorg_kernel(const float* __restrict__ stage5,
                                   const float* __restrict__ w1,
                                   const float* __restrict__ g1,
                                   const float* __restrict__ b1,
                                   const float* __restrict__ m1,
                                   const float* __restrict__ v1) {
    __shared__ float s5s[64 * 38 + 16];
    __shared__ float ws[64 * 68];

    const int y = blockIdx.x, b = blockIdx.y, tid = threadIdx.x;
    const int cg = tid & 15, xg = tid >> 4, cbase = cg * 4;

    float acc[4][5];
#pragma unroll
    for (int j = 0; j < 4; j++)
#pragma unroll
        for (int i = 0; i < 5; i++) acc[j][i] = 0.f;

    for (int ci0 = 0; ci0 < 512; ci0 += 64) {
        __syncthreads();
        for (int idx = tid; idx < 64 * 38; idx += 128) {
            int cc = idx / 38, xx = idx - cc * 38;
            s5s[idx] = stage5[((b * 512 + ci0 + cc) * 38 + y) * 38 + xx];
        }
        for (int idx = tid; idx < 64 * 64; idx += 128) {
            int c = idx >> 6, cc = idx & 63;
            ws[cc * 68 + c] = w1[c * 512 + ci0 + cc];
        }
        __syncthreads();
#pragma unroll 4
        for (int cc = 0; cc < 64; cc++) {
            float4 wv = *(const float4*)&ws[cc * 68 + cbase];
#pragma unroll
            for (int i = 0; i < 5; i++) {
                float sv = s5s[cc * 38 + xg + 8 * i];
                acc[0][i] += wv.x * sv;
                acc[1][i] += wv.y * sv;
                acc[2][i] += wv.z * sv;
                acc[3][i] += wv.w * sv;
            }
        }
    }

    const int sh = y & 1, ho = y >> 1;
#pragma unroll
    for (int j = 0; j < 4; j++) {
        int c = cbase + j;
        float sc = g1[c] * rsqrtf(v1[c] + BN_EPS);
        float sf = b1[c] - m1[c] * sc;
#pragma unroll
        for (int i = 0; i < 5; i++) {
            int x = xg + 8 * i;
            if (x < 38) {
                float v = acc[j][i] * sc + sf;
                v = v > 0.f ? v : SLOPE * v;
                int ch = sh * 128 + (x & 1) * 64 + c;
                int wo = x >> 1;
                int addr = ((b * 21 + 1 + ho) * 21 + 1 + wo) * 1280 + ch;
                bf16 hv, lv; split_bf16(v, hv, lv);
                g_cath[addr] = hv; g_catl[addr] = lv;
            }
        }
    }
}

// ---------------------------------------------------------------------------
// stage6 [32,1024,19,19] fp32 -> NHWC bf16 hi/lo at channels 256..1279
// ---------------------------------------------------------------------------
__global__ void stage6_to_cat(const float* __restrict__ s6) {
    __shared__ float t[32][33];
    const int b = blockIdx.z, c0 = blockIdx.y * 32, yx0 = blockIdx.x * 32;
    const int tx = threadIdx.x, ty0 = threadIdx.y;
#pragma unroll
    for (int i = 0; i < 4; i++) {
        int ty = ty0 + i * 8;
        int yx = yx0 + tx;
        t[ty][tx] = (yx < 361) ? s6[(b * 1024 + c0 + ty) * 361 + yx] : 0.f;
    }
    __syncthreads();
#pragma unroll
    for (int i = 0; i < 4; i++) {
        int ty = ty0 + i * 8;
        int yx = yx0 + ty;
        if (yx >= 361) continue;
        int y = yx / 19, x = yx - y * 19;
        float v = t[tx][ty];
        int addr = ((b * 21 + 1 + y) * 21 + 1 + x) * 1280 + 256 + c0 + tx;
        bf16 hv, lv; split_bf16(v, hv, lv);
        g_cath[addr] = hv; g_catl[addr] = lv;
    }
}

// ---------------------------------------------------------------------------
// Weight repacks
// ---------------------------------------------------------------------------
__global__ void repack_w2(const float* __restrict__ w2) {
    int idx = blockIdx.x * 256 + threadIdx.x;
    if (idx >= 1024 * K2) return;
    int co = idx / K2, kk = idx - co * K2;
    int rs = kk / 1280, ci = kk - rs * 1280;
    float v = w2[(co * 1280 + ci) * 9 + rs];
    bf16 hv, lv; split_bf16(v, hv, lv);
    g_w2h[idx] = hv; g_w2l[idx] = lv;
}

__global__ void repack_cls(const float* __restrict__ meta) {
    int idx = blockIdx.x * 256 + threadIdx.x;
    if (idx >= MHEAD_P * KH) return;
    int m = idx >> 10, k = idx & 1023;
    float v = (m < MHEAD) ? meta[m * 1025 + k] : 0.f;
    bf16 hv, lv; split_bf16(v, hv, lv);
    g_clsh[idx] = hv; g_clsl[idx] = lv;
}

// ---------------------------------------------------------------------------
// conv3x3 implicit GEMM on tensor cores. M=1024, N=11552, K=11520.
// CTA 128x128, 8 warps (2m x 4n), warp 64x32, K-step 32.
// 2-stage cp.async pipeline, 80KB SMEM/CTA -> 2 CTAs/SM.
// ---------------------------------------------------------------------------
#define SSTAGE 20480   // bf16 elements per stage (40960 bytes)

__global__ __launch_bounds__(256, 2)
void conv2_mma(const float* __restrict__ g2, const float* __restrict__ b2,
               const float* __restrict__ m2, const float* __restrict__ v2) {
    extern __shared__ bf16 dyn[];
    const int tid = threadIdx.x, lane = tid & 31, warp = tid >> 5;
    const int wm = warp >> 2, wn = warp & 3;
    const int gq = lane >> 2, tig = lane & 3;
    const int m0 = blockIdx.x * 128, p0 = blockIdx.y * 128;
    const int arow = tid >> 2, ach = tid & 3;

    int rbase[2];
#pragma unroll
    for (int it = 0; it < 2; ++it) {
        int p = p0 + arow + it * 64;
        if (p >= NPOS) p = NPOS - 1;
        int b = p / 361, yx = p - b * 361, y = yx / 19, x = yx - y * 19;
        rbase[it] = ((b * 21 + y) * 21 + x) * 1280;
    }

    float acc[4][4][4];
#pragma unroll
    for (int mf = 0; mf < 4; mf++)
#pragma unroll
        for (int nf = 0; nf < 4; nf++)
#pragma unroll
            for (int e = 0; e < 4; e++) acc[mf][nf][e] = 0.f;

#define CONV2_LOAD(KT)                                                         \
    do {                                                                       \
        int kt_ = (KT);                                                        \
        bf16* base_ = dyn + (kt_ & 1) * SSTAGE;                                \
        int k0_ = kt_ * 32;                                                    \
        _Pragma("unroll")                                                      \
        for (int it = 0; it < 2; ++it) {                                       \
            int r_ = arow + it * 64;                                           \
            cp16(base_ + r_ * 40 + ach * 8,        g_w2h + (m0 + r_) * K2 + k0_ + ach * 8); \
            cp16(base_ + 5120 + r_ * 40 + ach * 8, g_w2l + (m0 + r_) * K2 + k0_ + ach * 8); \
        }                                                                      \
        int rs_ = kt_ / 40, ci0_ = (kt_ - rs_ * 40) * 32;                      \
        int rr_ = rs_ / 3, ss_ = rs_ - rr_ * 3;                                \
        int koff_ = (rr_ * 21 + ss_) * 1280 + ci0_;                            \
        _Pragma("unroll")                                                      \
        for (int it = 0; it < 2; ++it) {                                       \
            int r_ = arow + it * 64;                                           \
            cp16(base_ + 10240 + r_ * 40 + ach * 8, g_cath + rbase[it] + koff_ + ach * 8); \
            cp16(base_ + 15360 + r_ * 40 + ach * 8, g_catl + rbase[it] + koff_ + ach * 8); \
        }                                                                      \
    } while (0)

    CONV2_LOAD(0); CPCOMMIT();
    for (int kt = 0; kt < KT2; ++kt) {
        if (kt + 1 < KT2) {
            CONV2_LOAD(kt + 1); CPCOMMIT(); CPWAIT1();
        } else {
            CPWAIT0();
        }
        __syncthreads();
        u32 sb = (u32)__cvta_generic_to_shared(dyn + (kt & 1) * SSTAGE);
        compute_stage(sb, lane, wm, wn, acc);
        __syncthreads();   // protect buf (kt&1) from next iteration's loads
    }
#undef CONV2_LOAD

    // Epilogue: BN + leaky, transpose to [pos][co], split to bf16 hi/lo.
    float* smf = (float*)dyn;            // [128 n][132 m] + sc[128] + sf[128]
#pragma unroll
    for (int mf = 0; mf < 4; ++mf)
#pragma unroll
        for (int nf = 0; nf < 4; ++nf)
#pragma unroll
            for (int e = 0; e < 4; ++e) {
                int m = wm * 64 + mf * 16 + gq + (e >> 1) * 8;
                int n = wn * 32 + nf * 8 + tig * 2 + (e & 1);
                smf[n * 132 + m] = acc[mf][nf][e];
            }
    if (tid < 128) {
        int co = m0 + tid;
        float sc = g2[co] * rsqrtf(v2[co] + BN_EPS);
        smf[128 * 132 + tid] = sc;
        smf[128 * 132 + 128 + tid] = b2[co] - m2[co] * sc;
    }
    __syncthreads();
    for (int idx = tid; idx < 128 * 128; idx += 256) {
        int n = idx >> 7, m = idx & 127;
        int p = p0 + n;
        if (p < NPOS) {
            float v = smf[n * 132 + m] * smf[128 * 132 + m] + smf[128 * 132 + 128 + m];
            v = v > 0.f ? v : SLOPE * v;
            bf16 hv, lv; split_bf16(v, hv, lv);
            int a = p * 1024 + m0 + m;
            g_preh[a] = hv; g_prel[a] = lv;
        }
    }
}

// ---------------------------------------------------------------------------
// Head GEMM: M=640(600), N=11552, K=1024. Same stage layout + compute.
// ---------------------------------------------------------------------------
__global__ __launch_bounds__(256, 2)
void head_mma(const float* __restrict__ meta, float* __restrict__ out) {
    extern __shared__ bf16 dyn[];
    const int tid = threadIdx.x, lane = tid & 31, warp = tid >> 5;
    const int wm = warp >> 2, wn = warp & 3;
    const int gq = lane >> 2, tig = lane & 3;
    const int m0 = blockIdx.x * 128, p0 = blockIdx.y * 128;
    const int arow = tid >> 2, ach = tid & 3;

    int rbase[2];
#pragma unroll
    for (int it = 0; it < 2; ++it) {
        int p = p0 + arow + it * 64;
        if (p >= NPOS) p = NPOS - 1;
        rbase[it] = p * KH;
    }

    float acc[4][4][4];
#pragma unroll
    for (int mf = 0; mf < 4; mf++)
#pragma unroll
        for (int nf = 0; nf < 4; nf++)
#pragma unroll
            for (int e = 0; e < 4; e++) acc[mf][nf][e] = 0.f;

#define HEAD_LOAD(KT)                                                          \
    do {                                                                       \
        int kt_ = (KT);                                                        \
        bf16* base_ = dyn + (kt_ & 1) * SSTAGE;                                \
        int k0_ = kt_ * 32;                                                    \
        _Pragma("unroll")                                                      \
        for (int it = 0; it < 2; ++it) {                                       \
            int r_ = arow + it * 64;                                           \
            cp16(base_ + r_ * 40 + ach * 8,         g_clsh + (m0 + r_) * KH + k0_ + ach * 8); \
            cp16(base_ + 5120 + r_ * 40 + ach * 8,  g_clsl + (m0 + r_) * KH + k0_ + ach * 8); \
            cp16(base_ + 10240 + r_ * 40 + ach * 8, g_preh + rbase[it] + k0_ + ach * 8); \
            cp16(base_ + 15360 + r_ * 40 + ach * 8, g_prel + rbase[it] + k0_ + ach * 8); \
        }                                                                      \
    } while (0)

    HEAD_LOAD(0); CPCOMMIT();
    for (int kt = 0; kt < KTH; ++kt) {
        if (kt + 1 < KTH) {
            HEAD_LOAD(kt + 1); CPCOMMIT(); CPWAIT1();
        } else {
            CPWAIT0();
        }
        __syncthreads();
        u32 sb = (u32)__cvta_generic_to_shared(dyn + (kt & 1) * SSTAGE);
        compute_stage(sb, lane, wm, wn, acc);
        __syncthreads();
    }
#undef HEAD_LOAD

    // Epilogue: + bias, scatter to out[(b*600+m)*361+yx]
#pragma unroll
    for (int mf = 0; mf < 4; ++mf) {
        int mb = m0 + wm * 64 + mf * 16 + gq;
#pragma unroll
        for (int e2 = 0; e2 < 2; ++e2) {
            int m = mb + e2 * 8;
            if (m < MHEAD) {
                float bias = meta[m * 1025 + 1024];
#pragma unroll
                for (int nf = 0; nf < 4; ++nf)
#pragma unroll
                    for (int e1 = 0; e1 < 2; ++e1) {
                        int n = p0 + wn * 32 + nf * 8 + tig * 2 + e1;
                        if (n < NPOS) {
                            int b = n / 361, yx = n - b * 361;
                            out[(b * 600 + m) * 361 + yx] = acc[mf][nf][e2 * 2 + e1] + bias;
                        }
                    }
            }
        }
    }
}

// ---------------------------------------------------------------------------
extern "C" void kernel_launch(void* const* d_in, const int* in_sizes, int n_in,
                              void* d_out, int out_size) {
    const float* stage6 = (const float*)d_in[0];
    const float* stage5 = (const float*)d_in[1];
    const float* w1     = (const float*)d_in[2];
    const float* g1     = (const float*)d_in[3];
    const float* b1     = (const float*)d_in[4];
    const float* m1     = (const float*)d_in[5];
    const float* v1     = (const float*)d_in[6];
    const float* w2     = (const float*)d_in[7];
    const float* g2     = (const float*)d_in[8];
    const float* b2     = (const float*)d_in[9];
    const float* m2     = (const float*)d_in[10];
    const float* v2     = (const float*)d_in[11];
    const float* meta   = (const float*)d_in[12];
    float* out = (float*)d_out;

    void* p;
    cudaGetSymbolAddress(&p, g_cath);
    cudaMemsetAsync(p, 0, sizeof(bf16) * BSZ * 441 * 1280, 0);
    cudaGetSymbolAddress(&p, g_catl);
    cudaMemsetAsync(p, 0, sizeof(bf16) * BSZ * 441 * 1280, 0);

    cudaFuncSetAttribute(conv2_mma, cudaFuncAttributeMaxDynamicSharedMemorySize, 2 * SSTAGE * 2);
    cudaFuncSetAttribute(head_mma,  cudaFuncAttributeMaxDynamicSharedMemorySize, 2 * SSTAGE * 2);

    // Order chosen so conv2_mma is the 6th launch (ncu -s 5 -c 1 captures it).
    repack_w2<<<(1024 * K2 + 255) / 256, 256>>>(w2);
    conv1_reorg_kernel<<<dim3(38, 32), 128>>>(stage5, w1, g1, b1, m1, v1);
    stage6_to_cat<<<dim3(12, 32, 32), dim3(32, 8)>>>(stage6);
    conv2_mma<<<dim3(8, 91), 256, 2 * SSTAGE * 2>>>(g2, b2, m2, v2);
    repack_cls<<<(MHEAD_P * KH + 255) / 256, 256>>>(meta);
    head_mma<<<dim3(5, 91), 256, 2 * SSTAGE * 2>>>(meta, out);
}

// round 11
// speedup vs baseline: 5.9307x; 2.1595x over previous
#include <cuda_runtime.h>
#include <cuda_bf16.h>
#include <cuda_fp16.h>
#include <stdint.h>
#include <math.h>

#define BN_EPS 1e-5f
#define SLOPE  0.1f
#define BSZ    32
#define HO     19
#define NPOS   (BSZ*HO*HO)    // 11552
#define K2     11520
#define NST2   (K2/32)        // 360
#define MHEAD  600
#define MHEAD_P 640
#define KH     1024
#define KTH    (KH/32)        // 32

typedef __nv_bfloat16 bf16;
typedef __half fp16;
typedef unsigned int u32;

// ---------------- device scratch (no allocs allowed) ----------------
__device__ fp16 g_cat[BSZ*21*21*1280];    // NHWC padded concat, fp16
__device__ fp16 g_w2[1024*K2];            // w2 repacked [co][(r*3+s)*1280+ci], fp16
__device__ bf16 g_clsh[MHEAD_P*KH];       // cls weights padded to 640 rows (bf16 hi)
__device__ bf16 g_clsl[MHEAD_P*KH];       // (bf16 lo)
__device__ bf16 g_preh[NPOS*KH];          // conv2 output [pos][co], bf16 hi
__device__ bf16 g_prel[NPOS*KH];          // bf16 lo

// ---------------- PTX helpers ----------------
__device__ __forceinline__ void ldm_x4(u32 addr, u32 &q0, u32 &q1, u32 &q2, u32 &q3) {
    asm volatile("ldmatrix.sync.aligned.m8n8.x4.shared.b16 {%0,%1,%2,%3}, [%4];"
                 : "=r"(q0), "=r"(q1), "=r"(q2), "=r"(q3) : "r"(addr));
}
__device__ __forceinline__ void mma_bf16(float* c, const u32* a, const u32* b) {
    asm volatile("mma.sync.aligned.m16n8k16.row.col.f32.bf16.bf16.f32 "
                 "{%0,%1,%2,%3}, {%4,%5,%6,%7}, {%8,%9}, {%0,%1,%2,%3};"
                 : "+f"(c[0]), "+f"(c[1]), "+f"(c[2]), "+f"(c[3])
                 : "r"(a[0]), "r"(a[1]), "r"(a[2]), "r"(a[3]), "r"(b[0]), "r"(b[1]));
}
__device__ __forceinline__ void mma_fp16(float* c, const u32* a, const u32* b) {
    asm volatile("mma.sync.aligned.m16n8k16.row.col.f32.f16.f16.f32 "
                 "{%0,%1,%2,%3}, {%4,%5,%6,%7}, {%8,%9}, {%0,%1,%2,%3};"
                 : "+f"(c[0]), "+f"(c[1]), "+f"(c[2]), "+f"(c[3])
                 : "r"(a[0]), "r"(a[1]), "r"(a[2]), "r"(a[3]), "r"(b[0]), "r"(b[1]));
}
__device__ __forceinline__ void cp16(void* dst, const void* src) {
    u32 d = (u32)__cvta_generic_to_shared(dst);
    asm volatile("cp.async.cg.shared.global [%0], [%1], 16;" :: "r"(d), "l"(src));
}
#define CPCOMMIT() asm volatile("cp.async.commit_group;")
#define CPWAIT1()  asm volatile("cp.async.wait_group 1;" ::: "memory")
#define CPWAIT0()  asm volatile("cp.async.wait_group 0;" ::: "memory")

__device__ __forceinline__ void split_bf16(float v, bf16& h, bf16& l) {
    h = __float2bfloat16(v);
    l = __float2bfloat16(v - __bfloat162float(h));
}

// ---------------------------------------------------------------------------
// fp16 single-term compute stage (conv2). Layout: A@0, B@10240 (bytes),
// row stride 80B (32 fp16 + 16B pad). Warp 64x32, 8 warps 2m x 4n.
// ---------------------------------------------------------------------------
__device__ __forceinline__ void compute_stage_fp16(u32 sb, int lane, int wm, int wn,
                                                   float (&acc)[4][4][4]) {
#pragma unroll
    for (int h = 0; h < 2; ++h) {
        u32 a[4][4], b[4][2];
#pragma unroll
        for (int mf = 0; mf < 4; ++mf) {
            int row = wm * 64 + mf * 16 + (lane & 15);
            u32 off = sb + row * 80 + h * 32 + (lane >> 4) * 16;
            ldm_x4(off, a[mf][0], a[mf][1], a[mf][2], a[mf][3]);
        }
#pragma unroll
        for (int nf2 = 0; nf2 < 2; ++nf2) {
            int row = wn * 32 + nf2 * 16 + (lane & 15);
            u32 off = sb + 10240 + row * 80 + h * 32 + (lane >> 4) * 16;
            u32 q0, q1, q2, q3;
            ldm_x4(off, q0, q1, q2, q3);
            b[nf2 * 2][0] = q0; b[nf2 * 2 + 1][0] = q1;
            b[nf2 * 2][1] = q2; b[nf2 * 2 + 1][1] = q3;
        }
#pragma unroll
        for (int mf = 0; mf < 4; ++mf)
#pragma unroll
            for (int nf = 0; nf < 4; ++nf)
                mma_fp16(acc[mf][nf], a[mf], b[nf]);
    }
}

// ---------------------------------------------------------------------------
// bf16 3-term compute stage (head). Layout: Ah@0, Al@10240, Bh@20480,
// Bl@30720 (bytes), row stride 80B.
// ---------------------------------------------------------------------------
__device__ __forceinline__ void compute_stage(u32 sb, int lane, int wm, int wn,
                                              float (&acc)[4][4][4]) {
#pragma unroll
    for (int h = 0; h < 2; ++h) {
        u32 aH[4][4], aL[4][4], bH[4][2], bL[4][2];
#pragma unroll
        for (int mf = 0; mf < 4; ++mf) {
            int row = wm * 64 + mf * 16 + (lane & 15);
            u32 off = sb + row * 80 + h * 32 + (lane >> 4) * 16;
            ldm_x4(off,         aH[mf][0], aH[mf][1], aH[mf][2], aH[mf][3]);
            ldm_x4(off + 10240, aL[mf][0], aL[mf][1], aL[mf][2], aL[mf][3]);
        }
#pragma unroll
        for (int nf2 = 0; nf2 < 2; ++nf2) {
            int row = wn * 32 + nf2 * 16 + (lane & 15);
            u32 off = sb + 20480 + row * 80 + h * 32 + (lane >> 4) * 16;
            u32 q0, q1, q2, q3;
            ldm_x4(off, q0, q1, q2, q3);
            bH[nf2 * 2][0] = q0; bH[nf2 * 2 + 1][0] = q1;
            bH[nf2 * 2][1] = q2; bH[nf2 * 2 + 1][1] = q3;
            u32 s0, s1, s2, s3;
            ldm_x4(off + 10240, s0, s1, s2, s3);
            bL[nf2 * 2][0] = s0; bL[nf2 * 2 + 1][0] = s1;
            bL[nf2 * 2][1] = s2; bL[nf2 * 2 + 1][1] = s3;
        }
#pragma unroll
        for (int mf = 0; mf < 4; ++mf)
#pragma unroll
            for (int nf = 0; nf < 4; ++nf) {
                mma_bf16(acc[mf][nf], aH[mf], bH[nf]);
                mma_bf16(acc[mf][nf], aH[mf], bL[nf]);
                mma_bf16(acc[mf][nf], aL[mf], bH[nf]);
            }
    }
}

// ---------------------------------------------------------------------------
// conv1x1(512->64)+BN+leaky+reorg(2) -> NHWC fp16, channels 0..255
// ---------------------------------------------------------------------------
__global__ void conv1_reorg_kernel(const float* __restrict__ stage5,
                                   const float* __restrict__ w1,
                                   const float* __restrict__ g1,
                                   const float* __restrict__ b1,
                                   const float* __restrict__ m1,
                                   const float* __restrict__ v1) {
    __shared__ float s5s[64 * 38 + 16];
    __shared__ float ws[64 * 68];

    const int y = blockIdx.x, b = blockIdx.y, tid = threadIdx.x;
    const int cg = tid & 15, xg = tid >> 4, cbase = cg * 4;

    float acc[4][5];
#pragma unroll
    for (int j = 0; j < 4; j++)
#pragma unroll
        for (int i = 0; i < 5; i++) acc[j][i] = 0.f;

    for (int ci0 = 0; ci0 < 512; ci0 += 64) {
        __syncthreads();
        for (int idx = tid; idx < 64 * 38; idx += 128) {
            int cc = idx / 38, xx = idx - cc * 38;
            s5s[idx] = stage5[((b * 512 + ci0 + cc) * 38 + y) * 38 + xx];
        }
        for (int idx = tid; idx < 64 * 64; idx += 128) {
            int c = idx >> 6, cc = idx & 63;
            ws[cc * 68 + c] = w1[c * 512 + ci0 + cc];
        }
        __syncthreads();
#pragma unroll 4
        for (int cc = 0; cc < 64; cc++) {
            float4 wv = *(const float4*)&ws[cc * 68 + cbase];
#pragma unroll
            for (int i = 0; i < 5; i++) {
                float sv = s5s[cc * 38 + xg + 8 * i];
                acc[0][i] += wv.x * sv;
                acc[1][i] += wv.y * sv;
                acc[2][i] += wv.z * sv;
                acc[3][i] += wv.w * sv;
            }
        }
    }

    const int sh = y & 1, ho = y >> 1;
#pragma unroll
    for (int j = 0; j < 4; j++) {
        int c = cbase + j;
        float sc = g1[c] * rsqrtf(v1[c] + BN_EPS);
        float sf = b1[c] - m1[c] * sc;
#pragma unroll
        for (int i = 0; i < 5; i++) {
            int x = xg + 8 * i;
            if (x < 38) {
                float v = acc[j][i] * sc + sf;
                v = v > 0.f ? v : SLOPE * v;
                int ch = sh * 128 + (x & 1) * 64 + c;
                int wo = x >> 1;
                g_cat[((b * 21 + 1 + ho) * 21 + 1 + wo) * 1280 + ch] = __float2half(v);
            }
        }
    }
}

// ---------------------------------------------------------------------------
// stage6 [32,1024,19,19] fp32 -> NHWC fp16 at channels 256..1279
// ---------------------------------------------------------------------------
__global__ void stage6_to_cat(const float* __restrict__ s6) {
    __shared__ float t[32][33];
    const int b = blockIdx.z, c0 = blockIdx.y * 32, yx0 = blockIdx.x * 32;
    const int tx = threadIdx.x, ty0 = threadIdx.y;
#pragma unroll
    for (int i = 0; i < 4; i++) {
        int ty = ty0 + i * 8;
        int yx = yx0 + tx;
        t[ty][tx] = (yx < 361) ? s6[(b * 1024 + c0 + ty) * 361 + yx] : 0.f;
    }
    __syncthreads();
#pragma unroll
    for (int i = 0; i < 4; i++) {
        int ty = ty0 + i * 8;
        int yx = yx0 + ty;
        if (yx >= 361) continue;
        int y = yx / 19, x = yx - y * 19;
        g_cat[((b * 21 + 1 + y) * 21 + 1 + x) * 1280 + 256 + c0 + tx] =
            __float2half(t[tx][ty]);
    }
}

// ---------------------------------------------------------------------------
// Weight repacks
// ---------------------------------------------------------------------------
__global__ void repack_w2(const float* __restrict__ w2) {
    int idx = blockIdx.x * 256 + threadIdx.x;
    if (idx >= 1024 * K2) return;
    int co = idx / K2, kk = idx - co * K2;
    int rs = kk / 1280, ci = kk - rs * 1280;
    g_w2[idx] = __float2half(w2[(co * 1280 + ci) * 9 + rs]);
}

__global__ void repack_cls(const float* __restrict__ meta) {
    int idx = blockIdx.x * 256 + threadIdx.x;
    if (idx >= MHEAD_P * KH) return;
    int m = idx >> 10, k = idx & 1023;
    float v = (m < MHEAD) ? meta[m * 1025 + k] : 0.f;
    bf16 hv, lv; split_bf16(v, hv, lv);
    g_clsh[idx] = hv; g_clsl[idx] = lv;
}

// ---------------------------------------------------------------------------
// conv3x3 implicit GEMM, fp16 single-term mma.sync. M=1024, N=11552, K=11520.
// CTA 128x128, 8 warps (2m x 4n), K-step 32, 2-stage cp.async, 2 CTAs/SM.
// Stage = 20480B (A 10240 + B 10240, 80B rows).
// ---------------------------------------------------------------------------
#define STG2 20480   // bytes per stage

__global__ __launch_bounds__(256, 2)
void conv2_fp16(const float* __restrict__ g2, const float* __restrict__ b2,
                const float* __restrict__ m2, const float* __restrict__ v2) {
    extern __shared__ char dyn[];
    const int tid = threadIdx.x, lane = tid & 31, warp = tid >> 5;
    const int wm = warp >> 2, wn = warp & 3;
    const int gq = lane >> 2, tig = lane & 3;
    const int m0 = blockIdx.x * 128, p0 = blockIdx.y * 128;
    const int rowq = tid >> 2, ch = tid & 3;   // row group 0..63, 16B chunk 0..3

    int rbase[2];
#pragma unroll
    for (int it = 0; it < 2; ++it) {
        int p = p0 + rowq + it * 64;
        if (p >= NPOS) p = NPOS - 1;
        int b = p / 361, yx = p - b * 361, y = yx / 19, x = yx - y * 19;
        rbase[it] = ((b * 21 + y) * 21 + x) * 1280;
    }

    float acc[4][4][4];
#pragma unroll
    for (int mf = 0; mf < 4; mf++)
#pragma unroll
        for (int nf = 0; nf < 4; nf++)
#pragma unroll
            for (int e = 0; e < 4; e++) acc[mf][nf][e] = 0.f;

#define CONV2_LOAD(KT)                                                         \
    do {                                                                       \
        int kt_ = (KT);                                                        \
        char* base_ = dyn + (kt_ & 1) * STG2;                                  \
        int k0_ = kt_ * 32;                                                    \
        int rs_ = kt_ / 40, ci0_ = (kt_ - rs_ * 40) * 32;                      \
        int rr_ = rs_ / 3, ss_ = rs_ - rr_ * 3;                                \
        int koff_ = (rr_ * 21 + ss_) * 1280 + ci0_;                            \
        _Pragma("unroll")                                                      \
        for (int it = 0; it < 2; ++it) {                                       \
            int r_ = rowq + it * 64;                                           \
            cp16(base_ + r_ * 80 + ch * 16,                                    \
                 g_w2 + (m0 + r_) * K2 + k0_ + ch * 8);                        \
            cp16(base_ + 10240 + r_ * 80 + ch * 16,                            \
                 g_cat + rbase[it] + koff_ + ch * 8);                          \
        }                                                                      \
    } while (0)

    CONV2_LOAD(0); CPCOMMIT();
    for (int kt = 0; kt < NST2; ++kt) {
        if (kt + 1 < NST2) {
            CONV2_LOAD(kt + 1); CPCOMMIT(); CPWAIT1();
        } else {
            CPWAIT0();
        }
        __syncthreads();
        u32 sb = (u32)__cvta_generic_to_shared(dyn + (kt & 1) * STG2);
        compute_stage_fp16(sb, lane, wm, wn, acc);
        __syncthreads();   // protect buf (kt&1) from next iteration's loads
    }
#undef CONV2_LOAD

    // Epilogue: BN + leaky, transpose to [pos][co], split to bf16 hi/lo.
    float* smf = (float*)dyn;            // [128 n][132 m] + sc[128] + sf[128]
#pragma unroll
    for (int mf = 0; mf < 4; ++mf)
#pragma unroll
        for (int nf = 0; nf < 4; ++nf)
#pragma unroll
            for (int e = 0; e < 4; ++e) {
                int m = wm * 64 + mf * 16 + gq + (e >> 1) * 8;
                int n = wn * 32 + nf * 8 + tig * 2 + (e & 1);
                smf[n * 132 + m] = acc[mf][nf][e];
            }
    if (tid < 128) {
        int co = m0 + tid;
        float sc = g2[co] * rsqrtf(v2[co] + BN_EPS);
        smf[128 * 132 + tid] = sc;
        smf[128 * 132 + 128 + tid] = b2[co] - m2[co] * sc;
    }
    __syncthreads();
    for (int idx = tid; idx < 128 * 128; idx += 256) {
        int n = idx >> 7, m = idx & 127;
        int p = p0 + n;
        if (p < NPOS) {
            float v = smf[n * 132 + m] * smf[128 * 132 + m] + smf[128 * 132 + 128 + m];
            v = v > 0.f ? v : SLOPE * v;
            bf16 hv, lv; split_bf16(v, hv, lv);
            int a = p * 1024 + m0 + m;
            g_preh[a] = hv; g_prel[a] = lv;
        }
    }
}

// ---------------------------------------------------------------------------
// Head GEMM (bf16 3-term mma.sync): M=640(600), N=11552, K=1024.
// ---------------------------------------------------------------------------
#define SSTAGE 20480   // bf16 elements per stage (40960 bytes)

__global__ __launch_bounds__(256, 2)
void head_mma(const float* __restrict__ meta, float* __restrict__ out) {
    extern __shared__ bf16 dynb[];
    const int tid = threadIdx.x, lane = tid & 31, warp = tid >> 5;
    const int wm = warp >> 2, wn = warp & 3;
    const int gq = lane >> 2, tig = lane & 3;
    const int m0 = blockIdx.x * 128, p0 = blockIdx.y * 128;
    const int arow = tid >> 2, ach = tid & 3;

    int rbase[2];
#pragma unroll
    for (int it = 0; it < 2; ++it) {
        int p = p0 + arow + it * 64;
        if (p >= NPOS) p = NPOS - 1;
        rbase[it] = p * KH;
    }

    float acc[4][4][4];
#pragma unroll
    for (int mf = 0; mf < 4; mf++)
#pragma unroll
        for (int nf = 0; nf < 4; nf++)
#pragma unroll
            for (int e = 0; e < 4; e++) acc[mf][nf][e] = 0.f;

#define HEAD_LOAD(KT)                                                          \
    do {                                                                       \
        int kt_ = (KT);                                                        \
        bf16* base_ = dynb + (kt_ & 1) * SSTAGE;                               \
        int k0_ = kt_ * 32;                                                    \
        _Pragma("unroll")                                                      \
        for (int it = 0; it < 2; ++it) {                                       \
            int r_ = arow + it * 64;                                           \
            cp16(base_ + r_ * 40 + ach * 8,         g_clsh + (m0 + r_) * KH + k0_ + ach * 8); \
            cp16(base_ + 5120 + r_ * 40 + ach * 8,  g_clsl + (m0 + r_) * KH + k0_ + ach * 8); \
            cp16(base_ + 10240 + r_ * 40 + ach * 8, g_preh + rbase[it] + k0_ + ach * 8); \
            cp16(base_ + 15360 + r_ * 40 + ach * 8, g_prel + rbase[it] + k0_ + ach * 8); \
        }                                                                      \
    } while (0)

    HEAD_LOAD(0); CPCOMMIT();
    for (int kt = 0; kt < KTH; ++kt) {
        if (kt + 1 < KTH) {
            HEAD_LOAD(kt + 1); CPCOMMIT(); CPWAIT1();
        } else {
            CPWAIT0();
        }
        __syncthreads();
        u32 sb = (u32)__cvta_generic_to_shared(dynb + (kt & 1) * SSTAGE);
        compute_stage(sb, lane, wm, wn, acc);
        __syncthreads();
    }
#undef HEAD_LOAD

    // Epilogue: + bias, scatter to out[(b*600+m)*361+yx]
#pragma unroll
    for (int mf = 0; mf < 4; ++mf) {
        int mb = m0 + wm * 64 + mf * 16 + gq;
#pragma unroll
        for (int e2 = 0; e2 < 2; ++e2) {
            int m = mb + e2 * 8;
            if (m < MHEAD) {
                float bias = meta[m * 1025 + 1024];
#pragma unroll
                for (int nf = 0; nf < 4; ++nf)
#pragma unroll
                    for (int e1 = 0; e1 < 2; ++e1) {
                        int n = p0 + wn * 32 + nf * 8 + tig * 2 + e1;
                        if (n < NPOS) {
                            int b = n / 361, yx = n - b * 361;
                            out[(b * 600 + m) * 361 + yx] = acc[mf][nf][e2 * 2 + e1] + bias;
                        }
                    }
            }
        }
    }
}

// ---------------------------------------------------------------------------
extern "C" void kernel_launch(void* const* d_in, const int* in_sizes, int n_in,
                              void* d_out, int out_size) {
    const float* stage6 = (const float*)d_in[0];
    const float* stage5 = (const float*)d_in[1];
    const float* w1     = (const float*)d_in[2];
    const float* g1     = (const float*)d_in[3];
    const float* b1     = (const float*)d_in[4];
    const float* m1     = (const float*)d_in[5];
    const float* v1     = (const float*)d_in[6];
    const float* w2     = (const float*)d_in[7];
    const float* g2     = (const float*)d_in[8];
    const float* b2     = (const float*)d_in[9];
    const float* m2     = (const float*)d_in[10];
    const float* v2     = (const float*)d_in[11];
    const float* meta   = (const float*)d_in[12];
    float* out = (float*)d_out;

    void* p;
    cudaGetSymbolAddress(&p, g_cat);
    cudaMemsetAsync(p, 0, sizeof(fp16) * BSZ * 441 * 1280, 0);

    // conv2 epilogue needs 128*132*4 + 1024 = 68608 bytes of dynamic smem
    cudaFuncSetAttribute(conv2_fp16, cudaFuncAttributeMaxDynamicSharedMemorySize, 68608);
    cudaFuncSetAttribute(head_mma,   cudaFuncAttributeMaxDynamicSharedMemorySize,
                         2 * SSTAGE * 2);

    // conv2_fp16 is the 6th launch (ncu -s 5 -c 1 captures it).
    repack_w2<<<(1024 * K2 + 255) / 256, 256>>>(w2);
    conv1_reorg_kernel<<<dim3(38, 32), 128>>>(stage5, w1, g1, b1, m1, v1);
    stage6_to_cat<<<dim3(12, 32, 32), dim3(32, 8)>>>(stage6);
    repack_cls<<<(MHEAD_P * KH + 255) / 256, 256>>>(meta);
    conv2_fp16<<<dim3(8, 91), 256, 68608>>>(g2, b2, m2, v2);
    head_mma<<<dim3(5, 91), 256, 2 * SSTAGE * 2>>>(meta, out);
}

// round 12
// speedup vs baseline: 6.3407x; 1.0691x over previous
#include <cuda_runtime.h>
#include <cuda_bf16.h>
#include <cuda_fp16.h>
#include <stdint.h>
#include <math.h>

#define BN_EPS 1e-5f
#define SLOPE  0.1f
#define BSZ    32
#define HO     19
#define NPOS   (BSZ*HO*HO)    // 11552
#define K2     11520
#define NST2   (K2/32)        // 360
#define MHEAD  600
#define MHEAD_P 640
#define KH     1024
#define KTH    (KH/32)        // 32

typedef __nv_bfloat16 bf16;
typedef __half fp16;
typedef unsigned int u32;

// ---------------- device scratch (no allocs allowed) ----------------
__device__ fp16 g_cat[BSZ*21*21*1280];    // NHWC padded concat, fp16
__device__ fp16 g_w2[1024*K2];            // w2 repacked [co][(r*3+s)*1280+ci], fp16
__device__ fp16 g_cls[MHEAD_P*KH];        // cls weights padded to 640 rows, fp16
__device__ fp16 g_pre[NPOS*KH];           // conv2 output [pos][co], fp16

// ---------------- PTX helpers ----------------
__device__ __forceinline__ void ldm_x4(u32 addr, u32 &q0, u32 &q1, u32 &q2, u32 &q3) {
    asm volatile("ldmatrix.sync.aligned.m8n8.x4.shared.b16 {%0,%1,%2,%3}, [%4];"
                 : "=r"(q0), "=r"(q1), "=r"(q2), "=r"(q3) : "r"(addr));
}
__device__ __forceinline__ void mma_fp16(float* c, const u32* a, const u32* b) {
    asm volatile("mma.sync.aligned.m16n8k16.row.col.f32.f16.f16.f32 "
                 "{%0,%1,%2,%3}, {%4,%5,%6,%7}, {%8,%9}, {%0,%1,%2,%3};"
                 : "+f"(c[0]), "+f"(c[1]), "+f"(c[2]), "+f"(c[3])
                 : "r"(a[0]), "r"(a[1]), "r"(a[2]), "r"(a[3]), "r"(b[0]), "r"(b[1]));
}
__device__ __forceinline__ void cp16(void* dst, const void* src) {
    u32 d = (u32)__cvta_generic_to_shared(dst);
    asm volatile("cp.async.cg.shared.global [%0], [%1], 16;" :: "r"(d), "l"(src));
}
#define CPCOMMIT() asm volatile("cp.async.commit_group;")
#define CPWAIT1()  asm volatile("cp.async.wait_group 1;" ::: "memory")
#define CPWAIT0()  asm volatile("cp.async.wait_group 0;" ::: "memory")

// ---------------------------------------------------------------------------
// fp16 single-term compute stage. Layout: A@0, B@10240 (bytes),
// row stride 80B (32 fp16 + 16B pad). Warp 64x32, 8 warps 2m x 4n.
// ---------------------------------------------------------------------------
__device__ __forceinline__ void compute_stage_fp16(u32 sb, int lane, int wm, int wn,
                                                   float (&acc)[4][4][4]) {
#pragma unroll
    for (int h = 0; h < 2; ++h) {
        u32 a[4][4], b[4][2];
#pragma unroll
        for (int mf = 0; mf < 4; ++mf) {
            int row = wm * 64 + mf * 16 + (lane & 15);
            u32 off = sb + row * 80 + h * 32 + (lane >> 4) * 16;
            ldm_x4(off, a[mf][0], a[mf][1], a[mf][2], a[mf][3]);
        }
#pragma unroll
        for (int nf2 = 0; nf2 < 2; ++nf2) {
            int row = wn * 32 + nf2 * 16 + (lane & 15);
            u32 off = sb + 10240 + row * 80 + h * 32 + (lane >> 4) * 16;
            u32 q0, q1, q2, q3;
            ldm_x4(off, q0, q1, q2, q3);
            b[nf2 * 2][0] = q0; b[nf2 * 2 + 1][0] = q1;
            b[nf2 * 2][1] = q2; b[nf2 * 2 + 1][1] = q3;
        }
#pragma unroll
        for (int mf = 0; mf < 4; ++mf)
#pragma unroll
            for (int nf = 0; nf < 4; ++nf)
                mma_fp16(acc[mf][nf], a[mf], b[nf]);
    }
}

// ---------------------------------------------------------------------------
// conv1x1(512->64)+BN+leaky+reorg(2) -> NHWC fp16, channels 0..255
// ---------------------------------------------------------------------------
__global__ void conv1_reorg_kernel(const float* __restrict__ stage5,
                                   const float* __restrict__ w1,
                                   const float* __restrict__ g1,
                                   const float* __restrict__ b1,
                                   const float* __restrict__ m1,
                                   const float* __restrict__ v1) {
    __shared__ float s5s[64 * 38 + 16];
    __shared__ float ws[64 * 68];

    const int y = blockIdx.x, b = blockIdx.y, tid = threadIdx.x;
    const int cg = tid & 15, xg = tid >> 4, cbase = cg * 4;

    float acc[4][5];
#pragma unroll
    for (int j = 0; j < 4; j++)
#pragma unroll
        for (int i = 0; i < 5; i++) acc[j][i] = 0.f;

    for (int ci0 = 0; ci0 < 512; ci0 += 64) {
        __syncthreads();
        for (int idx = tid; idx < 64 * 38; idx += 128) {
            int cc = idx / 38, xx = idx - cc * 38;
            s5s[idx] = stage5[((b * 512 + ci0 + cc) * 38 + y) * 38 + xx];
        }
        for (int idx = tid; idx < 64 * 64; idx += 128) {
            int c = idx >> 6, cc = idx & 63;
            ws[cc * 68 + c] = w1[c * 512 + ci0 + cc];
        }
        __syncthreads();
#pragma unroll 4
        for (int cc = 0; cc < 64; cc++) {
            float4 wv = *(const float4*)&ws[cc * 68 + cbase];
#pragma unroll
            for (int i = 0; i < 5; i++) {
                float sv = s5s[cc * 38 + xg + 8 * i];
                acc[0][i] += wv.x * sv;
                acc[1][i] += wv.y * sv;
                acc[2][i] += wv.z * sv;
                acc[3][i] += wv.w * sv;
            }
        }
    }

    const int sh = y & 1, ho = y >> 1;
#pragma unroll
    for (int j = 0; j < 4; j++) {
        int c = cbase + j;
        float sc = g1[c] * rsqrtf(v1[c] + BN_EPS);
        float sf = b1[c] - m1[c] * sc;
#pragma unroll
        for (int i = 0; i < 5; i++) {
            int x = xg + 8 * i;
            if (x < 38) {
                float v = acc[j][i] * sc + sf;
                v = v > 0.f ? v : SLOPE * v;
                int ch = sh * 128 + (x & 1) * 64 + c;
                int wo = x >> 1;
                g_cat[((b * 21 + 1 + ho) * 21 + 1 + wo) * 1280 + ch] = __float2half(v);
            }
        }
    }
}

// ---------------------------------------------------------------------------
// stage6 [32,1024,19,19] fp32 -> NHWC fp16 at channels 256..1279
// ---------------------------------------------------------------------------
__global__ void stage6_to_cat(const float* __restrict__ s6) {
    __shared__ float t[32][33];
    const int b = blockIdx.z, c0 = blockIdx.y * 32, yx0 = blockIdx.x * 32;
    const int tx = threadIdx.x, ty0 = threadIdx.y;
#pragma unroll
    for (int i = 0; i < 4; i++) {
        int ty = ty0 + i * 8;
        int yx = yx0 + tx;
        t[ty][tx] = (yx < 361) ? s6[(b * 1024 + c0 + ty) * 361 + yx] : 0.f;
    }
    __syncthreads();
#pragma unroll
    for (int i = 0; i < 4; i++) {
        int ty = ty0 + i * 8;
        int yx = yx0 + ty;
        if (yx >= 361) continue;
        int y = yx / 19, x = yx - y * 19;
        g_cat[((b * 21 + 1 + y) * 21 + 1 + x) * 1280 + 256 + c0 + tx] =
            __float2half(t[tx][ty]);
    }
}

// ---------------------------------------------------------------------------
// Weight repacks
// ---------------------------------------------------------------------------
__global__ void repack_w2(const float* __restrict__ w2) {
    int idx = blockIdx.x * 256 + threadIdx.x;
    if (idx >= 1024 * K2) return;
    int co = idx / K2, kk = idx - co * K2;
    int rs = kk / 1280, ci = kk - rs * 1280;
    g_w2[idx] = __float2half(w2[(co * 1280 + ci) * 9 + rs]);
}

__global__ void repack_cls(const float* __restrict__ meta) {
    int idx = blockIdx.x * 256 + threadIdx.x;
    if (idx >= MHEAD_P * KH) return;
    int m = idx >> 10, k = idx & 1023;
    g_cls[idx] = __float2half((m < MHEAD) ? meta[m * 1025 + k] : 0.f);
}

// ---------------------------------------------------------------------------
// conv3x3 implicit GEMM, fp16 single-term mma.sync. M=1024, N=11552, K=11520.
// CTA 128x128, 8 warps (2m x 4n), K-step 32, 2-stage cp.async, 2 CTAs/SM.
// Stage = 20480B (A 10240 + B 10240, 80B rows).
// ---------------------------------------------------------------------------
#define STG2 20480   // bytes per stage

__global__ __launch_bounds__(256, 2)
void conv2_fp16(const float* __restrict__ g2, const float* __restrict__ b2,
                const float* __restrict__ m2, const float* __restrict__ v2) {
    extern __shared__ char dyn[];
    const int tid = threadIdx.x, lane = tid & 31, warp = tid >> 5;
    const int wm = warp >> 2, wn = warp & 3;
    const int gq = lane >> 2, tig = lane & 3;
    const int m0 = blockIdx.x * 128, p0 = blockIdx.y * 128;
    const int rowq = tid >> 2, ch = tid & 3;   // row group 0..63, 16B chunk 0..3

    int rbase[2];
#pragma unroll
    for (int it = 0; it < 2; ++it) {
        int p = p0 + rowq + it * 64;
        if (p >= NPOS) p = NPOS - 1;
        int b = p / 361, yx = p - b * 361, y = yx / 19, x = yx - y * 19;
        rbase[it] = ((b * 21 + y) * 21 + x) * 1280;
    }

    float acc[4][4][4];
#pragma unroll
    for (int mf = 0; mf < 4; mf++)
#pragma unroll
        for (int nf = 0; nf < 4; nf++)
#pragma unroll
            for (int e = 0; e < 4; e++) acc[mf][nf][e] = 0.f;

#define CONV2_LOAD(KT)                                                         \
    do {                                                                       \
        int kt_ = (KT);                                                        \
        char* base_ = dyn + (kt_ & 1) * STG2;                                  \
        int k0_ = kt_ * 32;                                                    \
        int rs_ = kt_ / 40, ci0_ = (kt_ - rs_ * 40) * 32;                      \
        int rr_ = rs_ / 3, ss_ = rs_ - rr_ * 3;                                \
        int koff_ = (rr_ * 21 + ss_) * 1280 + ci0_;                            \
        _Pragma("unroll")                                                      \
        for (int it = 0; it < 2; ++it) {                                       \
            int r_ = rowq + it * 64;                                           \
            cp16(base_ + r_ * 80 + ch * 16,                                    \
                 g_w2 + (m0 + r_) * K2 + k0_ + ch * 8);                        \
            cp16(base_ + 10240 + r_ * 80 + ch * 16,                            \
                 g_cat + rbase[it] + koff_ + ch * 8);                          \
        }                                                                      \
    } while (0)

    CONV2_LOAD(0); CPCOMMIT();
    for (int kt = 0; kt < NST2; ++kt) {
        if (kt + 1 < NST2) {
            CONV2_LOAD(kt + 1); CPCOMMIT(); CPWAIT1();
        } else {
            CPWAIT0();
        }
        __syncthreads();
        u32 sb = (u32)__cvta_generic_to_shared(dyn + (kt & 1) * STG2);
        compute_stage_fp16(sb, lane, wm, wn, acc);
        __syncthreads();   // protect buf (kt&1) from next iteration's loads
    }
#undef CONV2_LOAD

    // Epilogue: BN + leaky, transpose to [pos][co], store fp16.
    float* smf = (float*)dyn;            // [128 n][132 m] + sc[128] + sf[128]
#pragma unroll
    for (int mf = 0; mf < 4; ++mf)
#pragma unroll
        for (int nf = 0; nf < 4; ++nf)
#pragma unroll
            for (int e = 0; e < 4; ++e) {
                int m = wm * 64 + mf * 16 + gq + (e >> 1) * 8;
                int n = wn * 32 + nf * 8 + tig * 2 + (e & 1);
                smf[n * 132 + m] = acc[mf][nf][e];
            }
    if (tid < 128) {
        int co = m0 + tid;
        float sc = g2[co] * rsqrtf(v2[co] + BN_EPS);
        smf[128 * 132 + tid] = sc;
        smf[128 * 132 + 128 + tid] = b2[co] - m2[co] * sc;
    }
    __syncthreads();
    for (int idx = tid; idx < 128 * 128; idx += 256) {
        int n = idx >> 7, m = idx & 127;
        int p = p0 + n;
        if (p < NPOS) {
            float v = smf[n * 132 + m] * smf[128 * 132 + m] + smf[128 * 132 + 128 + m];
            v = v > 0.f ? v : SLOPE * v;
            g_pre[p * 1024 + m0 + m] = __float2half(v);
        }
    }
}

// ---------------------------------------------------------------------------
// Head GEMM (fp16 single-term): M=640(600), N=11552, K=1024.
// Same skeleton/stage layout as conv2_fp16.
// ---------------------------------------------------------------------------
__global__ __launch_bounds__(256, 2)
void head_fp16(const float* __restrict__ meta, float* __restrict__ out) {
    extern __shared__ char dyn[];
    const int tid = threadIdx.x, lane = tid & 31, warp = tid >> 5;
    const int wm = warp >> 2, wn = warp & 3;
    const int gq = lane >> 2, tig = lane & 3;
    const int m0 = blockIdx.x * 128, p0 = blockIdx.y * 128;
    const int rowq = tid >> 2, ch = tid & 3;

    int rbase[2];
#pragma unroll
    for (int it = 0; it < 2; ++it) {
        int p = p0 + rowq + it * 64;
        if (p >= NPOS) p = NPOS - 1;
        rbase[it] = p * KH;
    }

    float acc[4][4][4];
#pragma unroll
    for (int mf = 0; mf < 4; mf++)
#pragma unroll
        for (int nf = 0; nf < 4; nf++)
#pragma unroll
            for (int e = 0; e < 4; e++) acc[mf][nf][e] = 0.f;

#define HEAD_LOAD(KT)                                                          \
    do {                                                                       \
        int kt_ = (KT);                                                        \
        char* base_ = dyn + (kt_ & 1) * STG2;                                  \
        int k0_ = kt_ * 32;                                                    \
        _Pragma("unroll")                                                      \
        for (int it = 0; it < 2; ++it) {                                       \
            int r_ = rowq + it * 64;                                           \
            cp16(base_ + r_ * 80 + ch * 16,                                    \
                 g_cls + (m0 + r_) * KH + k0_ + ch * 8);                       \
            cp16(base_ + 10240 + r_ * 80 + ch * 16,                            \
                 g_pre + rbase[it] + k0_ + ch * 8);                            \
        }                                                                      \
    } while (0)

    HEAD_LOAD(0); CPCOMMIT();
    for (int kt = 0; kt < KTH; ++kt) {
        if (kt + 1 < KTH) {
            HEAD_LOAD(kt + 1); CPCOMMIT(); CPWAIT1();
        } else {
            CPWAIT0();
        }
        __syncthreads();
        u32 sb = (u32)__cvta_generic_to_shared(dyn + (kt & 1) * STG2);
        compute_stage_fp16(sb, lane, wm, wn, acc);
        __syncthreads();
    }
#undef HEAD_LOAD

    // Epilogue: + bias, scatter to out[(b*600+m)*361+yx]
#pragma unroll
    for (int mf = 0; mf < 4; ++mf) {
        int mb = m0 + wm * 64 + mf * 16 + gq;
#pragma unroll
        for (int e2 = 0; e2 < 2; ++e2) {
            int m = mb + e2 * 8;
            if (m < MHEAD) {
                float bias = meta[m * 1025 + 1024];
#pragma unroll
                for (int nf = 0; nf < 4; ++nf)
#pragma unroll
                    for (int e1 = 0; e1 < 2; ++e1) {
                        int n = p0 + wn * 32 + nf * 8 + tig * 2 + e1;
                        if (n < NPOS) {
                            int b = n / 361, yx = n - b * 361;
                            out[(b * 600 + m) * 361 + yx] = acc[mf][nf][e2 * 2 + e1] + bias;
                        }
                    }
            }
        }
    }
}

// ---------------------------------------------------------------------------
extern "C" void kernel_launch(void* const* d_in, const int* in_sizes, int n_in,
                              void* d_out, int out_size) {
    const float* stage6 = (const float*)d_in[0];
    const float* stage5 = (const float*)d_in[1];
    const float* w1     = (const float*)d_in[2];
    const float* g1     = (const float*)d_in[3];
    const float* b1     = (const float*)d_in[4];
    const float* m1     = (const float*)d_in[5];
    const float* v1     = (const float*)d_in[6];
    const float* w2     = (const float*)d_in[7];
    const float* g2     = (const float*)d_in[8];
    const float* b2     = (const float*)d_in[9];
    const float* m2     = (const float*)d_in[10];
    const float* v2     = (const float*)d_in[11];
    const float* meta   = (const float*)d_in[12];
    float* out = (float*)d_out;

    void* p;
    cudaGetSymbolAddress(&p, g_cat);
    cudaMemsetAsync(p, 0, sizeof(fp16) * BSZ * 441 * 1280, 0);

    // conv2 epilogue needs 128*132*4 + 1024 = 68608 bytes of dynamic smem
    cudaFuncSetAttribute(conv2_fp16, cudaFuncAttributeMaxDynamicSharedMemorySize, 68608);
    cudaFuncSetAttribute(head_fp16,  cudaFuncAttributeMaxDynamicSharedMemorySize, 2 * STG2);

    // conv2_fp16 is the 4th kernel launch (observed ncu capture slot).
    repack_w2<<<(1024 * K2 + 255) / 256, 256>>>(w2);
    conv1_reorg_kernel<<<dim3(38, 32), 128>>>(stage5, w1, g1, b1, m1, v1);
    stage6_to_cat<<<dim3(12, 32, 32), dim3(32, 8)>>>(stage6);
    conv2_fp16<<<dim3(8, 91), 256, 68608>>>(g2, b2, m2, v2);
    repack_cls<<<(MHEAD_P * KH + 255) / 256, 256>>>(meta);
    head_fp16<<<dim3(5, 91), 256, 2 * STG2>>>(meta, out);
}

// round 13
// speedup vs baseline: 6.3608x; 1.0032x over previous
#include <cuda_runtime.h>
#include <cuda_bf16.h>
#include <cuda_fp16.h>
#include <stdint.h>
#include <math.h>

#define BN_EPS 1e-5f
#define SLOPE  0.1f
#define BSZ    32
#define HO     19
#define NPOS   (BSZ*HO*HO)    // 11552
#define K2     11520
#define NST2   (K2/32)        // 360
#define MHEAD  600
#define MHEAD_P 640
#define KH     1024
#define KTH    (KH/32)        // 32

typedef __nv_bfloat16 bf16;
typedef __half fp16;
typedef unsigned int u32;

// ---------------- device scratch (no allocs allowed) ----------------
__device__ fp16 g_cat[BSZ*21*21*1280];    // NHWC padded concat, fp16
__device__ fp16 g_w2[1024*K2];            // w2 repacked [co][(r*3+s)*1280+ci], fp16
__device__ fp16 g_cls[MHEAD_P*KH];        // cls weights padded to 640 rows, fp16
__device__ fp16 g_pre[NPOS*KH];           // conv2 output [pos][co], fp16

// ---------------- PTX helpers ----------------
__device__ __forceinline__ void ldm_x4(u32 addr, u32 &q0, u32 &q1, u32 &q2, u32 &q3) {
    asm volatile("ldmatrix.sync.aligned.m8n8.x4.shared.b16 {%0,%1,%2,%3}, [%4];"
                 : "=r"(q0), "=r"(q1), "=r"(q2), "=r"(q3) : "r"(addr));
}
__device__ __forceinline__ void mma_fp16(float* c, const u32* a, const u32* b) {
    asm volatile("mma.sync.aligned.m16n8k16.row.col.f32.f16.f16.f32 "
                 "{%0,%1,%2,%3}, {%4,%5,%6,%7}, {%8,%9}, {%0,%1,%2,%3};"
                 : "+f"(c[0]), "+f"(c[1]), "+f"(c[2]), "+f"(c[3])
                 : "r"(a[0]), "r"(a[1]), "r"(a[2]), "r"(a[3]), "r"(b[0]), "r"(b[1]));
}
__device__ __forceinline__ void cp16(void* dst, const void* src) {
    u32 d = (u32)__cvta_generic_to_shared(dst);
    asm volatile("cp.async.cg.shared.global [%0], [%1], 16;" :: "r"(d), "l"(src));
}
#define CPCOMMIT() asm volatile("cp.async.commit_group;")
#define CPWAIT1()  asm volatile("cp.async.wait_group 1;" ::: "memory")
#define CPWAIT0()  asm volatile("cp.async.wait_group 0;" ::: "memory")

// ---------------------------------------------------------------------------
// fp16 single-term compute stage. Layout: A@0, B@10240 (bytes),
// row stride 80B (32 fp16 + 16B pad). Warp 64x32, 8 warps 2m x 4n.
// ---------------------------------------------------------------------------
__device__ __forceinline__ void compute_stage_fp16(u32 sb, int lane, int wm, int wn,
                                                   float (&acc)[4][4][4]) {
#pragma unroll
    for (int h = 0; h < 2; ++h) {
        u32 a[4][4], b[4][2];
#pragma unroll
        for (int mf = 0; mf < 4; ++mf) {
            int row = wm * 64 + mf * 16 + (lane & 15);
            u32 off = sb + row * 80 + h * 32 + (lane >> 4) * 16;
            ldm_x4(off, a[mf][0], a[mf][1], a[mf][2], a[mf][3]);
        }
#pragma unroll
        for (int nf2 = 0; nf2 < 2; ++nf2) {
            int row = wn * 32 + nf2 * 16 + (lane & 15);
            u32 off = sb + 10240 + row * 80 + h * 32 + (lane >> 4) * 16;
            u32 q0, q1, q2, q3;
            ldm_x4(off, q0, q1, q2, q3);
            b[nf2 * 2][0] = q0; b[nf2 * 2 + 1][0] = q1;
            b[nf2 * 2][1] = q2; b[nf2 * 2 + 1][1] = q3;
        }
#pragma unroll
        for (int mf = 0; mf < 4; ++mf)
#pragma unroll
            for (int nf = 0; nf < 4; ++nf)
                mma_fp16(acc[mf][nf], a[mf], b[nf]);
    }
}

// ---------------------------------------------------------------------------
// conv1x1(512->64)+BN+leaky+reorg(2) -> NHWC fp16, channels 0..255
// ---------------------------------------------------------------------------
__global__ void conv1_reorg_kernel(const float* __restrict__ stage5,
                                   const float* __restrict__ w1,
                                   const float* __restrict__ g1,
                                   const float* __restrict__ b1,
                                   const float* __restrict__ m1,
                                   const float* __restrict__ v1) {
    __shared__ float s5s[64 * 38 + 16];
    __shared__ float ws[64 * 68];

    const int y = blockIdx.x, b = blockIdx.y, tid = threadIdx.x;
    const int cg = tid & 15, xg = tid >> 4, cbase = cg * 4;

    float acc[4][5];
#pragma unroll
    for (int j = 0; j < 4; j++)
#pragma unroll
        for (int i = 0; i < 5; i++) acc[j][i] = 0.f;

    for (int ci0 = 0; ci0 < 512; ci0 += 64) {
        __syncthreads();
        for (int idx = tid; idx < 64 * 38; idx += 128) {
            int cc = idx / 38, xx = idx - cc * 38;
            s5s[idx] = stage5[((b * 512 + ci0 + cc) * 38 + y) * 38 + xx];
        }
        for (int idx = tid; idx < 64 * 64; idx += 128) {
            int c = idx >> 6, cc = idx & 63;
            ws[cc * 68 + c] = w1[c * 512 + ci0 + cc];
        }
        __syncthreads();
#pragma unroll 4
        for (int cc = 0; cc < 64; cc++) {
            float4 wv = *(const float4*)&ws[cc * 68 + cbase];
#pragma unroll
            for (int i = 0; i < 5; i++) {
                float sv = s5s[cc * 38 + xg + 8 * i];
                acc[0][i] += wv.x * sv;
                acc[1][i] += wv.y * sv;
                acc[2][i] += wv.z * sv;
                acc[3][i] += wv.w * sv;
            }
        }
    }

    const int sh = y & 1, ho = y >> 1;
#pragma unroll
    for (int j = 0; j < 4; j++) {
        int c = cbase + j;
        float sc = g1[c] * rsqrtf(v1[c] + BN_EPS);
        float sf = b1[c] - m1[c] * sc;
#pragma unroll
        for (int i = 0; i < 5; i++) {
            int x = xg + 8 * i;
            if (x < 38) {
                float v = acc[j][i] * sc + sf;
                v = v > 0.f ? v : SLOPE * v;
                int ch = sh * 128 + (x & 1) * 64 + c;
                int wo = x >> 1;
                g_cat[((b * 21 + 1 + ho) * 21 + 1 + wo) * 1280 + ch] = __float2half(v);
            }
        }
    }
}

// ---------------------------------------------------------------------------
// stage6 [32,1024,19,19] fp32 -> NHWC fp16 at channels 256..1279
// ---------------------------------------------------------------------------
__global__ void stage6_to_cat(const float* __restrict__ s6) {
    __shared__ float t[32][33];
    const int b = blockIdx.z, c0 = blockIdx.y * 32, yx0 = blockIdx.x * 32;
    const int tx = threadIdx.x, ty0 = threadIdx.y;
#pragma unroll
    for (int i = 0; i < 4; i++) {
        int ty = ty0 + i * 8;
        int yx = yx0 + tx;
        t[ty][tx] = (yx < 361) ? s6[(b * 1024 + c0 + ty) * 361 + yx] : 0.f;
    }
    __syncthreads();
#pragma unroll
    for (int i = 0; i < 4; i++) {
        int ty = ty0 + i * 8;
        int yx = yx0 + ty;
        if (yx >= 361) continue;
        int y = yx / 19, x = yx - y * 19;
        g_cat[((b * 21 + 1 + y) * 21 + 1 + x) * 1280 + 256 + c0 + tx] =
            __float2half(t[tx][ty]);
    }
}

// ---------------------------------------------------------------------------
// Weight repacks
// ---------------------------------------------------------------------------
__global__ void repack_w2(const float* __restrict__ w2) {
    int idx = blockIdx.x * 256 + threadIdx.x;
    if (idx >= 1024 * K2) return;
    int co = idx / K2, kk = idx - co * K2;
    int rs = kk / 1280, ci = kk - rs * 1280;
    g_w2[idx] = __float2half(w2[(co * 1280 + ci) * 9 + rs]);
}

__global__ void repack_cls(const float* __restrict__ meta) {
    int idx = blockIdx.x * 256 + threadIdx.x;
    if (idx >= MHEAD_P * KH) return;
    int m = idx >> 10, k = idx & 1023;
    g_cls[idx] = __float2half((m < MHEAD) ? meta[m * 1025 + k] : 0.f);
}

// ---------------------------------------------------------------------------
// conv3x3 implicit GEMM, fp16 single-term mma.sync. M=1024, N=11552, K=11520.
// CTA 128x128, 8 warps (2m x 4n), K-step 32, 3-stage cp.async, ONE barrier
// per K-step, 60KB smem -> 2 CTAs/SM. Stage = 20480B (A 10240 + B 10240).
// ---------------------------------------------------------------------------
#define STG2 20480   // bytes per stage

__global__ __launch_bounds__(256, 2)
void conv2_fp16(const float* __restrict__ g2, const float* __restrict__ b2,
                const float* __restrict__ m2, const float* __restrict__ v2) {
    extern __shared__ char dyn[];
    const int tid = threadIdx.x, lane = tid & 31, warp = tid >> 5;
    const int wm = warp >> 2, wn = warp & 3;
    const int gq = lane >> 2, tig = lane & 3;
    const int m0 = blockIdx.x * 128, p0 = blockIdx.y * 128;
    const int rowq = tid >> 2, ch = tid & 3;   // row group 0..63, 16B chunk 0..3

    int rbase[2];
#pragma unroll
    for (int it = 0; it < 2; ++it) {
        int p = p0 + rowq + it * 64;
        if (p >= NPOS) p = NPOS - 1;
        int b = p / 361, yx = p - b * 361, y = yx / 19, x = yx - y * 19;
        rbase[it] = ((b * 21 + y) * 21 + x) * 1280;
    }

    float acc[4][4][4];
#pragma unroll
    for (int mf = 0; mf < 4; mf++)
#pragma unroll
        for (int nf = 0; nf < 4; nf++)
#pragma unroll
            for (int e = 0; e < 4; e++) acc[mf][nf][e] = 0.f;

#define CONV2_LOAD(KT)                                                         \
    do {                                                                       \
        int kt_ = (KT);                                                        \
        char* base_ = dyn + (kt_ % 3) * STG2;                                  \
        int k0_ = kt_ * 32;                                                    \
        int rs_ = kt_ / 40, ci0_ = (kt_ - rs_ * 40) * 32;                      \
        int rr_ = rs_ / 3, ss_ = rs_ - rr_ * 3;                                \
        int koff_ = (rr_ * 21 + ss_) * 1280 + ci0_;                            \
        _Pragma("unroll")                                                      \
        for (int it = 0; it < 2; ++it) {                                       \
            int r_ = rowq + it * 64;                                           \
            cp16(base_ + r_ * 80 + ch * 16,                                    \
                 g_w2 + (m0 + r_) * K2 + k0_ + ch * 8);                        \
            cp16(base_ + 10240 + r_ * 80 + ch * 16,                            \
                 g_cat + rbase[it] + koff_ + ch * 8);                          \
        }                                                                      \
    } while (0)

    CONV2_LOAD(0); CPCOMMIT();
    CONV2_LOAD(1); CPCOMMIT();
    for (int kt = 0; kt < NST2; ++kt) {
        if (kt + 2 < NST2) { CPWAIT1(); } else { CPWAIT0(); }
        __syncthreads();
        // load stage kt+2 into buffer (kt+2)%3 == (kt-1)%3 — every thread
        // finished compute(kt-1) before this barrier, so overwrite is safe.
        if (kt + 2 < NST2) { CONV2_LOAD(kt + 2); CPCOMMIT(); }
        u32 sb = (u32)__cvta_generic_to_shared(dyn + (kt % 3) * STG2);
        compute_stage_fp16(sb, lane, wm, wn, acc);
    }
#undef CONV2_LOAD

    // Epilogue: BN + leaky, transpose to [pos][co], store fp16.
    __syncthreads();
    float* smf = (float*)dyn;            // [128 n][132 m] + sc[128] + sf[128]
#pragma unroll
    for (int mf = 0; mf < 4; ++mf)
#pragma unroll
        for (int nf = 0; nf < 4; ++nf)
#pragma unroll
            for (int e = 0; e < 4; ++e) {
                int m = wm * 64 + mf * 16 + gq + (e >> 1) * 8;
                int n = wn * 32 + nf * 8 + tig * 2 + (e & 1);
                smf[n * 132 + m] = acc[mf][nf][e];
            }
    if (tid < 128) {
        int co = m0 + tid;
        float sc = g2[co] * rsqrtf(v2[co] + BN_EPS);
        smf[128 * 132 + tid] = sc;
        smf[128 * 132 + 128 + tid] = b2[co] - m2[co] * sc;
    }
    __syncthreads();
    for (int idx = tid; idx < 128 * 128; idx += 256) {
        int n = idx >> 7, m = idx & 127;
        int p = p0 + n;
        if (p < NPOS) {
            float v = smf[n * 132 + m] * smf[128 * 132 + m] + smf[128 * 132 + 128 + m];
            v = v > 0.f ? v : SLOPE * v;
            g_pre[p * 1024 + m0 + m] = __float2half(v);
        }
    }
}

// ---------------------------------------------------------------------------
// Head GEMM (fp16 single-term): M=640(600), N=11552, K=1024.
// Same 3-stage single-barrier pipeline.
// ---------------------------------------------------------------------------
__global__ __launch_bounds__(256, 2)
void head_fp16(const float* __restrict__ meta, float* __restrict__ out) {
    extern __shared__ char dyn[];
    const int tid = threadIdx.x, lane = tid & 31, warp = tid >> 5;
    const int wm = warp >> 2, wn = warp & 3;
    const int gq = lane >> 2, tig = lane & 3;
    const int m0 = blockIdx.x * 128, p0 = blockIdx.y * 128;
    const int rowq = tid >> 2, ch = tid & 3;

    int rbase[2];
#pragma unroll
    for (int it = 0; it < 2; ++it) {
        int p = p0 + rowq + it * 64;
        if (p >= NPOS) p = NPOS - 1;
        rbase[it] = p * KH;
    }

    float acc[4][4][4];
#pragma unroll
    for (int mf = 0; mf < 4; mf++)
#pragma unroll
        for (int nf = 0; nf < 4; nf++)
#pragma unroll
            for (int e = 0; e < 4; e++) acc[mf][nf][e] = 0.f;

#define HEAD_LOAD(KT)                                                          \
    do {                                                                       \
        int kt_ = (KT);                                                        \
        char* base_ = dyn + (kt_ % 3) * STG2;                                  \
        int k0_ = kt_ * 32;                                                    \
        _Pragma("unroll")                                                      \
        for (int it = 0; it < 2; ++it) {                                       \
            int r_ = rowq + it * 64;                                           \
            cp16(base_ + r_ * 80 + ch * 16,                                    \
                 g_cls + (m0 + r_) * KH + k0_ + ch * 8);                       \
            cp16(base_ + 10240 + r_ * 80 + ch * 16,                            \
                 g_pre + rbase[it] + k0_ + ch * 8);                            \
        }                                                                      \
    } while (0)

    HEAD_LOAD(0); CPCOMMIT();
    HEAD_LOAD(1); CPCOMMIT();
    for (int kt = 0; kt < KTH; ++kt) {
        if (kt + 2 < KTH) { CPWAIT1(); } else { CPWAIT0(); }
        __syncthreads();
        if (kt + 2 < KTH) { HEAD_LOAD(kt + 2); CPCOMMIT(); }
        u32 sb = (u32)__cvta_generic_to_shared(dyn + (kt % 3) * STG2);
        compute_stage_fp16(sb, lane, wm, wn, acc);
    }
#undef HEAD_LOAD

    // Epilogue: + bias, scatter to out[(b*600+m)*361+yx]
#pragma unroll
    for (int mf = 0; mf < 4; ++mf) {
        int mb = m0 + wm * 64 + mf * 16 + gq;
#pragma unroll
        for (int e2 = 0; e2 < 2; ++e2) {
            int m = mb + e2 * 8;
            if (m < MHEAD) {
                float bias = meta[m * 1025 + 1024];
#pragma unroll
                for (int nf = 0; nf < 4; ++nf)
#pragma unroll
                    for (int e1 = 0; e1 < 2; ++e1) {
                        int n = p0 + wn * 32 + nf * 8 + tig * 2 + e1;
                        if (n < NPOS) {
                            int b = n / 361, yx = n - b * 361;
                            out[(b * 600 + m) * 361 + yx] = acc[mf][nf][e2 * 2 + e1] + bias;
                        }
                    }
            }
        }
    }
}

// ---------------------------------------------------------------------------
extern "C" void kernel_launch(void* const* d_in, const int* in_sizes, int n_in,
                              void* d_out, int out_size) {
    const float* stage6 = (const float*)d_in[0];
    const float* stage5 = (const float*)d_in[1];
    const float* w1     = (const float*)d_in[2];
    const float* g1     = (const float*)d_in[3];
    const float* b1     = (const float*)d_in[4];
    const float* m1     = (const float*)d_in[5];
    const float* v1     = (const float*)d_in[6];
    const float* w2     = (const float*)d_in[7];
    const float* g2     = (const float*)d_in[8];
    const float* b2     = (const float*)d_in[9];
    const float* m2     = (const float*)d_in[10];
    const float* v2     = (const float*)d_in[11];
    const float* meta   = (const float*)d_in[12];
    float* out = (float*)d_out;

    void* p;
    cudaGetSymbolAddress(&p, g_cat);
    cudaMemsetAsync(p, 0, sizeof(fp16) * BSZ * 441 * 1280, 0);

    // conv2: max(3*20480 pipeline, 68608 epilogue) = 68608 bytes dynamic smem
    cudaFuncSetAttribute(conv2_fp16, cudaFuncAttributeMaxDynamicSharedMemorySize, 68608);
    cudaFuncSetAttribute(head_fp16,  cudaFuncAttributeMaxDynamicSharedMemorySize, 3 * STG2);

    // conv2_fp16 is the 4th kernel launch (observed ncu capture slot).
    repack_w2<<<(1024 * K2 + 255) / 256, 256>>>(w2);
    conv1_reorg_kernel<<<dim3(38, 32), 128>>>(stage5, w1, g1, b1, m1, v1);
    stage6_to_cat<<<dim3(12, 32, 32), dim3(32, 8)>>>(stage6);
    conv2_fp16<<<dim3(8, 91), 256, 68608>>>(g2, b2, m2, v2);
    repack_cls<<<(MHEAD_P * KH + 255) / 256, 256>>>(meta);
    head_fp16<<<dim3(5, 91), 256, 3 * STG2>>>(meta, out);
}